// round 1
// baseline (speedup 1.0000x reference)
#include <cuda_runtime.h>

// Problem constants
#define BB   2
#define NN   2048
#define MM   1024
#define HH   16
#define DKK  64
#define ROWS (BB*NN)   // 4096

// Scratch (allocation-free rule: __device__ globals)
__device__ float g_q[BB*HH*NN*DKK];
__device__ float g_k[BB*HH*NN*DKK];
__device__ float g_v[BB*HH*NN*DKK];
__device__ float g_att[BB*NN*MM];

// ---------------------------------------------------------------------------
// GEMM: C[r,c] = sum_k A[r,k] * W[c,k] + bias[c]
// A: [ROWS, MM] row-major, W: [MM, MM] row-major (we multiply by W^T).
// headed=1: scatter into [B,H,N,DK] layout. headed=0: flat [ROWS, MM].
// Tile 64x64, BK=16, 256 threads, 4x4 per thread.
// ---------------------------------------------------------------------------
__global__ __launch_bounds__(256) void gemm_bias_kernel(
    const float* __restrict__ A, const float* __restrict__ W,
    const float* __restrict__ bias, float* __restrict__ C, int headed)
{
    __shared__ float As[16][65];
    __shared__ float Bs[16][65];

    const int tid  = threadIdx.x;
    const int ty   = tid >> 4;          // 0..15
    const int tx   = tid & 15;          // 0..15
    const int row0 = blockIdx.y * 64;
    const int col0 = blockIdx.x * 64;
    const int lr   = tid >> 2;          // 0..63  (tile row / tile col for loads)
    const int lk   = (tid & 3) << 2;    // 0,4,8,12

    float acc[4][4] = {};

    const float* Aptr = A + (size_t)(row0 + lr) * MM + lk;
    const float* Wptr = W + (size_t)(col0 + lr) * MM + lk;

    for (int k0 = 0; k0 < MM; k0 += 16) {
        float4 a = *(const float4*)(Aptr + k0);
        float4 w = *(const float4*)(Wptr + k0);
        As[lk+0][lr] = a.x; As[lk+1][lr] = a.y; As[lk+2][lr] = a.z; As[lk+3][lr] = a.w;
        Bs[lk+0][lr] = w.x; Bs[lk+1][lr] = w.y; Bs[lk+2][lr] = w.z; Bs[lk+3][lr] = w.w;
        __syncthreads();

        #pragma unroll
        for (int kk = 0; kk < 16; kk++) {
            float af[4], bf[4];
            #pragma unroll
            for (int i = 0; i < 4; i++) af[i] = As[kk][ty*4 + i];
            #pragma unroll
            for (int j = 0; j < 4; j++) bf[j] = Bs[kk][tx*4 + j];
            #pragma unroll
            for (int i = 0; i < 4; i++)
                #pragma unroll
                for (int j = 0; j < 4; j++)
                    acc[i][j] += af[i] * bf[j];
        }
        __syncthreads();
    }

    #pragma unroll
    for (int i = 0; i < 4; i++) {
        const int row = row0 + ty*4 + i;
        #pragma unroll
        for (int j = 0; j < 4; j++) {
            const int col = col0 + tx*4 + j;
            const float v = acc[i][j] + bias[col];
            if (headed) {
                const int b = row >> 11;          // /NN
                const int n = row & (NN - 1);
                const int h = col >> 6;           // /DKK
                const int d = col & (DKK - 1);
                C[(((size_t)(b*HH + h))*NN + n)*DKK + d] = v;
            } else {
                C[(size_t)row * MM + col] = v;
            }
        }
    }
}

// ---------------------------------------------------------------------------
// Flash attention with multiplicative pre-softmax mask.
// One CTA: (b, h, q-tile of 64). 256 threads = 16x16, 4x4 micro-tiles.
// Online softmax; row stats replicated across the 16 lanes that own a q-row
// (half-warp shuffles). Output written directly in concat [B,N,M] layout.
// smem: Qs, Ks, Vs, Ps each 64x65 floats (padded) -> 66,560 B dynamic.
// ---------------------------------------------------------------------------
#define PAD 65

__global__ __launch_bounds__(256) void flash_attn_kernel(
    const float* __restrict__ mask, float* __restrict__ out)
{
    extern __shared__ float sm[];
    float* Qs = sm;                 // [64][65]
    float* Ks = Qs + 64*PAD;
    float* Vs = Ks + 64*PAD;
    float* Ps = Vs + 64*PAD;

    const int tid = threadIdx.x;
    const int ty  = tid >> 4;
    const int tx  = tid & 15;
    const int q0  = blockIdx.x * 64;
    const int h   = blockIdx.y;
    const int b   = blockIdx.z;

    const float* Qg = g_q + (((size_t)(b*HH + h))*NN) * DKK;
    const float* Kg = g_k + (((size_t)(b*HH + h))*NN) * DKK;
    const float* Vg = g_v + (((size_t)(b*HH + h))*NN) * DKK;
    const float* Mg = mask + (size_t)b * NN * NN;

    // Load Q tile (64 x 64), row-major in smem with pad
    #pragma unroll
    for (int i = tid; i < 64*16; i += 256) {
        const int r  = i >> 4;
        const int c4 = (i & 15) << 2;
        float4 v = *(const float4*)(Qg + (size_t)(q0 + r)*DKK + c4);
        Qs[r*PAD + c4+0] = v.x; Qs[r*PAD + c4+1] = v.y;
        Qs[r*PAD + c4+2] = v.z; Qs[r*PAD + c4+3] = v.w;
    }

    float o[4][4] = {};
    float m_old[4] = {-1e30f, -1e30f, -1e30f, -1e30f};
    float l[4] = {};

    for (int k0 = 0; k0 < NN; k0 += 64) {
        // Load K, V tiles
        #pragma unroll
        for (int i = tid; i < 64*16; i += 256) {
            const int r  = i >> 4;
            const int c4 = (i & 15) << 2;
            float4 kv = *(const float4*)(Kg + (size_t)(k0 + r)*DKK + c4);
            float4 vv = *(const float4*)(Vg + (size_t)(k0 + r)*DKK + c4);
            Ks[r*PAD + c4+0] = kv.x; Ks[r*PAD + c4+1] = kv.y;
            Ks[r*PAD + c4+2] = kv.z; Ks[r*PAD + c4+3] = kv.w;
            Vs[r*PAD + c4+0] = vv.x; Vs[r*PAD + c4+1] = vv.y;
            Vs[r*PAD + c4+2] = vv.z; Vs[r*PAD + c4+3] = vv.w;
        }
        __syncthreads();

        // S = Q @ K^T  (4x4 per thread)
        float s[4][4] = {};
        #pragma unroll
        for (int d = 0; d < 64; d++) {
            float qf[4], kf[4];
            #pragma unroll
            for (int i = 0; i < 4; i++) qf[i] = Qs[(ty*4 + i)*PAD + d];
            #pragma unroll
            for (int j = 0; j < 4; j++) kf[j] = Ks[(tx*4 + j)*PAD + d];
            #pragma unroll
            for (int i = 0; i < 4; i++)
                #pragma unroll
                for (int j = 0; j < 4; j++)
                    s[i][j] += qf[i] * kf[j];
        }

        // scale + multiplicative mask
        #pragma unroll
        for (int i = 0; i < 4; i++) {
            const size_t mrow = (size_t)(q0 + ty*4 + i) * NN + k0 + tx*4;
            float4 mk = *(const float4*)(Mg + mrow);
            s[i][0] = s[i][0] * 0.125f * mk.x;
            s[i][1] = s[i][1] * 0.125f * mk.y;
            s[i][2] = s[i][2] * 0.125f * mk.z;
            s[i][3] = s[i][3] * 0.125f * mk.w;
        }

        // online softmax update (row stats shared across 16 lanes of same ty)
        float m_new[4], rs[4];
        #pragma unroll
        for (int i = 0; i < 4; i++) {
            float mx = fmaxf(fmaxf(s[i][0], s[i][1]), fmaxf(s[i][2], s[i][3]));
            #pragma unroll
            for (int off = 8; off > 0; off >>= 1)
                mx = fmaxf(mx, __shfl_xor_sync(0xffffffffu, mx, off));
            m_new[i] = fmaxf(m_old[i], mx);
            const float corr = __expf(m_old[i] - m_new[i]);
            l[i] *= corr;
            #pragma unroll
            for (int j = 0; j < 4; j++) o[i][j] *= corr;

            float rsum = 0.f;
            #pragma unroll
            for (int j = 0; j < 4; j++) {
                const float p = __expf(s[i][j] - m_new[i]);
                s[i][j] = p;
                rsum += p;
            }
            rs[i] = rsum;
            m_old[i] = m_new[i];
        }
        #pragma unroll
        for (int i = 0; i < 4; i++) {
            float rsum = rs[i];
            #pragma unroll
            for (int off = 8; off > 0; off >>= 1)
                rsum += __shfl_xor_sync(0xffffffffu, rsum, off);
            l[i] += rsum;
        }

        // stash P tile to smem
        __syncthreads();   // (Ps reuse across iterations: ensure prior PV reads done)
        #pragma unroll
        for (int i = 0; i < 4; i++)
            #pragma unroll
            for (int j = 0; j < 4; j++)
                Ps[(ty*4 + i)*PAD + tx*4 + j] = s[i][j];
        __syncthreads();

        // O += P @ V
        #pragma unroll
        for (int c = 0; c < 64; c++) {
            float pf[4], vf[4];
            #pragma unroll
            for (int i = 0; i < 4; i++) pf[i] = Ps[(ty*4 + i)*PAD + c];
            #pragma unroll
            for (int j = 0; j < 4; j++) vf[j] = Vs[c*PAD + tx*4 + j];
            #pragma unroll
            for (int i = 0; i < 4; i++)
                #pragma unroll
                for (int j = 0; j < 4; j++)
                    o[i][j] += pf[i] * vf[j];
        }
        __syncthreads();   // before overwriting Ks/Vs next iteration
    }

    // normalize and write to concat layout [B, N, M]
    #pragma unroll
    for (int i = 0; i < 4; i++) {
        const float inv_l = 1.0f / l[i];
        float4 v;
        v.x = o[i][0] * inv_l;
        v.y = o[i][1] * inv_l;
        v.z = o[i][2] * inv_l;
        v.w = o[i][3] * inv_l;
        *(float4*)(out + (size_t)(b*NN + q0 + ty*4 + i) * MM + h*DKK + tx*4) = v;
    }
}

// ---------------------------------------------------------------------------
extern "C" void kernel_launch(void* const* d_in, const int* in_sizes, int n_in,
                              void* d_out, int out_size)
{
    const float* x    = (const float*)d_in[0];
    const float* mask = (const float*)d_in[1];
    const float* Wq   = (const float*)d_in[2];
    const float* bq   = (const float*)d_in[3];
    const float* Wk   = (const float*)d_in[4];
    const float* bk   = (const float*)d_in[5];
    const float* Wv   = (const float*)d_in[6];
    const float* bv   = (const float*)d_in[7];
    const float* Wo   = (const float*)d_in[8];
    const float* bo   = (const float*)d_in[9];
    float* out = (float*)d_out;

    void *pq, *pk, *pv, *pa;
    cudaGetSymbolAddress(&pq, g_q);
    cudaGetSymbolAddress(&pk, g_k);
    cudaGetSymbolAddress(&pv, g_v);
    cudaGetSymbolAddress(&pa, g_att);

    const int smem_flash = 4 * 64 * PAD * (int)sizeof(float);
    cudaFuncSetAttribute(flash_attn_kernel,
                         cudaFuncAttributeMaxDynamicSharedMemorySize, smem_flash);

    dim3 gemm_grid(MM/64, ROWS/64);  // (16, 64)

    // Q/K/V projections -> head-split layout
    gemm_bias_kernel<<<gemm_grid, 256>>>(x, Wq, bq, (float*)pq, 1);
    gemm_bias_kernel<<<gemm_grid, 256>>>(x, Wk, bk, (float*)pk, 1);
    gemm_bias_kernel<<<gemm_grid, 256>>>(x, Wv, bv, (float*)pv, 1);

    // fused attention -> concat layout
    dim3 attn_grid(NN/64, HH, BB);   // (32, 16, 2)
    flash_attn_kernel<<<attn_grid, 256, smem_flash>>>(mask, (float*)pa);

    // output projection -> d_out
    gemm_bias_kernel<<<gemm_grid, 256>>>((const float*)pa, Wo, bo, out, 0);
}

// round 3
// speedup vs baseline: 2.5675x; 2.5675x over previous
#include <cuda_runtime.h>

// Problem constants
#define BB   2
#define NN   2048
#define MM   1024
#define HH   16
#define DKK  64
#define ROWS (BB*NN)   // 4096

// Scratch (allocation-free rule: __device__ globals)
__device__ float g_q[BB*HH*NN*DKK];
__device__ float g_k[BB*HH*NN*DKK];
__device__ float g_v[BB*HH*NN*DKK];
__device__ float g_att[BB*NN*MM];

// ===========================================================================
// Helpers
// ===========================================================================
__device__ __forceinline__ unsigned f2tf32(float x) {
    unsigned r;
    asm("cvt.rna.tf32.f32 %0, %1;" : "=r"(r) : "f"(x));
    return r;
}

// m16n8k8 tf32 MMA: D += A(16x8) * B(8x8).
// A frag: a0=(g,t) a1=(g+8,t) a2=(g,t+4) a3=(g+8,t+4); B: b0=(k=t,n=g) b1=(k=t+4,n=g)
// C: c0=(g,2t) c1=(g,2t+1) c2=(g+8,2t) c3=(g+8,2t+1)   [g=lane>>2, t=lane&3]
__device__ __forceinline__ void mma8(float* d, unsigned a0, unsigned a1,
                                     unsigned a2, unsigned a3,
                                     unsigned b0, unsigned b1)
{
    asm("mma.sync.aligned.m16n8k8.row.col.f32.tf32.tf32.f32 "
        "{%0,%1,%2,%3},{%4,%5,%6,%7},{%8,%9},{%0,%1,%2,%3};"
        : "+f"(d[0]), "+f"(d[1]), "+f"(d[2]), "+f"(d[3])
        : "r"(a0), "r"(a1), "r"(a2), "r"(a3), "r"(b0), "r"(b1));
}

// FMA-pipe exp (no MUFU). Valid for x <= 0 (softmax args); ~1e-7 rel accuracy.
__device__ __forceinline__ float fast_exp(float x) {
    float z = fmaxf(x * 1.4426950408889634f, -126.0f);
    float zi = z + 12582912.0f;              // round-to-nearest int in mantissa
    int   n  = __float_as_int(zi);           // low bits carry the integer
    float f  = z - (zi - 12582912.0f);       // f in [-0.5, 0.5]
    float p  = 1.33335581e-3f;
    p = p * f + 9.61812911e-3f;
    p = p * f + 5.55041087e-2f;
    p = p * f + 2.40226512e-1f;
    p = p * f + 6.93147182e-1f;
    p = p * f + 1.0f;
    return __int_as_float(__float_as_int(p) + (n << 23));
}

// ===========================================================================
// Tensor-core tf32 GEMM: C[r,c] = sum_k A[r,k]*W[c,k] + bias[c]
// CTA 128x128, 8 warps (2x4), warp tile 64x32, K-chunk 32, double buffer.
// smem stride 36 floats -> fragment LDS bank = (4g+t)%32, conflict-free.
// ===========================================================================
#define GSTR 36
#define GBUF (128*GSTR)          // 4608 floats per operand buffer
#define GEMM_SMEM (4*GBUF*4)     // 73728 bytes

__device__ __forceinline__ void gemm_load_chunk(
    const float* __restrict__ A, const float* __restrict__ W,
    float* Ab, float* Wb, int tid, int row0, int col0, int chunk)
{
    #pragma unroll
    for (int u = 0; u < 4; u++) {
        const int uu = tid + u * 256;
        const int r  = uu >> 3;
        const int cc = (uu & 7) << 2;
        float4 va = *(const float4*)(A + (size_t)(row0 + r) * MM + chunk * 32 + cc);
        float4 vw = *(const float4*)(W + (size_t)(col0 + r) * MM + chunk * 32 + cc);
        uint4 ta = { f2tf32(va.x), f2tf32(va.y), f2tf32(va.z), f2tf32(va.w) };
        uint4 tw = { f2tf32(vw.x), f2tf32(vw.y), f2tf32(vw.z), f2tf32(vw.w) };
        *(uint4*)(Ab + r * GSTR + cc) = ta;
        *(uint4*)(Wb + r * GSTR + cc) = tw;
    }
}

__global__ __launch_bounds__(256) void gemm_mma_kernel(
    const float* __restrict__ A, const float* __restrict__ W,
    const float* __restrict__ bias, float* __restrict__ C, int headed)
{
    extern __shared__ float gs[];
    // layout: Abuf0 [0,4608), Abuf1 [4608,9216), Wbuf0 [9216,13824), Wbuf1 [13824,18432)

    const int tid  = threadIdx.x;
    const int w    = tid >> 5;
    const int lane = tid & 31;
    const int g    = lane >> 2;
    const int t    = lane & 3;
    const int row0 = blockIdx.y * 128;
    const int col0 = blockIdx.x * 128;
    const int wm   = (w >> 2) * 64;   // warp row offset
    const int wn   = (w & 3) * 32;    // warp col offset

    float c[4][4][4] = {};

    gemm_load_chunk(A, W, gs, gs + 2*GBUF, tid, row0, col0, 0);
    __syncthreads();

    for (int i = 0; i < 32; i++) {
        const int cur = i & 1;
        if (i + 1 < 32) {
            gemm_load_chunk(A, W, gs + (1 - cur) * GBUF, gs + 2*GBUF + (1 - cur) * GBUF,
                            tid, row0, col0, i + 1);
        }
        const float* Ab = gs + cur * GBUF;
        const float* Wb = gs + 2*GBUF + cur * GBUF;

        #pragma unroll
        for (int ks = 0; ks < 4; ks++) {
            const int kb = ks * 8;
            unsigned a[4][4];
            #pragma unroll
            for (int mt = 0; mt < 4; mt++) {
                const float* ar = Ab + (wm + mt * 16 + g) * GSTR + kb;
                a[mt][0] = __float_as_uint(ar[t]);
                a[mt][1] = __float_as_uint(ar[8 * GSTR + t]);
                a[mt][2] = __float_as_uint(ar[t + 4]);
                a[mt][3] = __float_as_uint(ar[8 * GSTR + t + 4]);
            }
            #pragma unroll
            for (int nt = 0; nt < 4; nt++) {
                const float* br = Wb + (wn + nt * 8 + g) * GSTR + kb;
                const unsigned b0 = __float_as_uint(br[t]);
                const unsigned b1 = __float_as_uint(br[t + 4]);
                #pragma unroll
                for (int mt = 0; mt < 4; mt++)
                    mma8(c[mt][nt], a[mt][0], a[mt][1], a[mt][2], a[mt][3], b0, b1);
            }
        }
        __syncthreads();
    }

    // Epilogue
    #pragma unroll
    for (int mt = 0; mt < 4; mt++) {
        const int r0 = row0 + wm + mt * 16 + g;
        const int r1 = r0 + 8;
        #pragma unroll
        for (int nt = 0; nt < 4; nt++) {
            const int col = col0 + wn + nt * 8 + 2 * t;
            const float bx = bias[col], by = bias[col + 1];
            float2 v0 = { c[mt][nt][0] + bx, c[mt][nt][1] + by };
            float2 v1 = { c[mt][nt][2] + bx, c[mt][nt][3] + by };
            if (headed) {
                const int h = col >> 6;
                const int d = col & 63;
                const int b0r = r0 >> 11, n0r = r0 & (NN - 1);
                const int b1r = r1 >> 11, n1r = r1 & (NN - 1);
                *(float2*)(C + (((size_t)(b0r*HH + h))*NN + n0r)*DKK + d) = v0;
                *(float2*)(C + (((size_t)(b1r*HH + h))*NN + n1r)*DKK + d) = v1;
            } else {
                *(float2*)(C + (size_t)r0 * MM + col) = v0;
                *(float2*)(C + (size_t)r1 * MM + col) = v1;
            }
        }
    }
}

// ===========================================================================
// Flash attention, mma.sync tf32. CTA = 64 q-rows, 4 warps (warp = 16 rows).
// kv tile 64. smem stride 68 -> all fragment LDS conflict-free.
// ===========================================================================
#define FSTR 68
#define FLASH_SMEM (4 * 64 * FSTR * 4)   // Qs,Ks,Vs,Ps = 69632 bytes

__global__ __launch_bounds__(128) void flash_mma_kernel(
    const float* __restrict__ mask, float* __restrict__ out)
{
    extern __shared__ float fs[];
    float* Qs = fs;                  // [64][68]
    float* Ks = Qs + 64 * FSTR;
    float* Vs = Ks + 64 * FSTR;
    float* Ps = Vs + 64 * FSTR;

    const int tid  = threadIdx.x;
    const int w    = tid >> 5;
    const int lane = tid & 31;
    const int g    = lane >> 2;
    const int t    = lane & 3;
    const int q0   = blockIdx.x * 64;
    const int h    = blockIdx.y;
    const int b    = blockIdx.z;

    const float* Qg = g_q + (((size_t)(b*HH + h)) * NN) * DKK;
    const float* Kg = g_k + (((size_t)(b*HH + h)) * NN) * DKK;
    const float* Vg = g_v + (((size_t)(b*HH + h)) * NN) * DKK;
    const float* Mg = mask + (size_t)b * NN * NN;

    // Q tile, 1/sqrt(dk)=0.125 folded in, tf32
    for (int u = tid; u < 64 * 16; u += 128) {
        const int r  = u >> 4;
        const int cc = (u & 15) << 2;
        float4 v = *(const float4*)(Qg + (size_t)(q0 + r) * DKK + cc);
        uint4 tv = { f2tf32(v.x * 0.125f), f2tf32(v.y * 0.125f),
                     f2tf32(v.z * 0.125f), f2tf32(v.w * 0.125f) };
        *(uint4*)(Qs + r * FSTR + cc) = tv;
    }

    float o[8][4] = {};
    float m0 = -1e30f, m1 = -1e30f;
    float l0 = 0.f, l1 = 0.f;

    const int qr0 = q0 + w * 16 + g;        // this thread's first q row

    for (int k0 = 0; k0 < NN; k0 += 64) {
        __syncthreads();   // prior PV reads of Vs done
        for (int u = tid; u < 64 * 16; u += 128) {
            const int r  = u >> 4;
            const int cc = (u & 15) << 2;
            float4 kv = *(const float4*)(Kg + (size_t)(k0 + r) * DKK + cc);
            float4 vv = *(const float4*)(Vg + (size_t)(k0 + r) * DKK + cc);
            uint4 tk = { f2tf32(kv.x), f2tf32(kv.y), f2tf32(kv.z), f2tf32(kv.w) };
            uint4 tv = { f2tf32(vv.x), f2tf32(vv.y), f2tf32(vv.z), f2tf32(vv.w) };
            *(uint4*)(Ks + r * FSTR + cc) = tk;
            *(uint4*)(Vs + r * FSTR + cc) = tv;
        }
        __syncthreads();

        // S = Q * K^T   (S tile rows w*16..w*16+15, cols 0..63)
        float s[8][4];
        #pragma unroll
        for (int nt = 0; nt < 8; nt++)
            s[nt][0] = s[nt][1] = s[nt][2] = s[nt][3] = 0.f;

        #pragma unroll
        for (int ks = 0; ks < 8; ks++) {
            const int kb = ks * 8;
            const float* ar = Qs + (w * 16 + g) * FSTR + kb;
            const unsigned a0 = __float_as_uint(ar[t]);
            const unsigned a1 = __float_as_uint(ar[8 * FSTR + t]);
            const unsigned a2 = __float_as_uint(ar[t + 4]);
            const unsigned a3 = __float_as_uint(ar[8 * FSTR + t + 4]);
            #pragma unroll
            for (int nt = 0; nt < 8; nt++) {
                const float* br = Ks + (nt * 8 + g) * FSTR + kb;
                mma8(s[nt], a0, a1, a2, a3,
                     __float_as_uint(br[t]), __float_as_uint(br[t + 4]));
            }
        }

        // multiplicative mask
        {
            const float* Mr0 = Mg + (size_t)qr0 * NN + k0;
            const float* Mr1 = Mr0 + 8 * NN;
            #pragma unroll
            for (int nt = 0; nt < 8; nt++) {
                float2 ma = *(const float2*)(Mr0 + nt * 8 + 2 * t);
                float2 mb = *(const float2*)(Mr1 + nt * 8 + 2 * t);
                s[nt][0] *= ma.x; s[nt][1] *= ma.y;
                s[nt][2] *= mb.x; s[nt][3] *= mb.y;
            }
        }

        // online softmax (rows qr0 and qr0+8); row group = 4 lanes (t)
        float mx0 = -1e30f, mx1 = -1e30f;
        #pragma unroll
        for (int nt = 0; nt < 8; nt++) {
            mx0 = fmaxf(mx0, fmaxf(s[nt][0], s[nt][1]));
            mx1 = fmaxf(mx1, fmaxf(s[nt][2], s[nt][3]));
        }
        mx0 = fmaxf(mx0, __shfl_xor_sync(0xffffffffu, mx0, 1));
        mx0 = fmaxf(mx0, __shfl_xor_sync(0xffffffffu, mx0, 2));
        mx1 = fmaxf(mx1, __shfl_xor_sync(0xffffffffu, mx1, 1));
        mx1 = fmaxf(mx1, __shfl_xor_sync(0xffffffffu, mx1, 2));

        const float mn0 = fmaxf(m0, mx0);
        const float mn1 = fmaxf(m1, mx1);
        const float cr0 = fast_exp(m0 - mn0);
        const float cr1 = fast_exp(m1 - mn1);
        l0 *= cr0; l1 *= cr1;
        m0 = mn0;  m1 = mn1;

        float r0 = 0.f, r1 = 0.f;
        #pragma unroll
        for (int nt = 0; nt < 8; nt++) {
            o[nt][0] *= cr0; o[nt][1] *= cr0;
            o[nt][2] *= cr1; o[nt][3] *= cr1;
            s[nt][0] = fast_exp(s[nt][0] - mn0);
            s[nt][1] = fast_exp(s[nt][1] - mn0);
            s[nt][2] = fast_exp(s[nt][2] - mn1);
            s[nt][3] = fast_exp(s[nt][3] - mn1);
            r0 += s[nt][0] + s[nt][1];
            r1 += s[nt][2] + s[nt][3];
        }
        r0 += __shfl_xor_sync(0xffffffffu, r0, 1);
        r0 += __shfl_xor_sync(0xffffffffu, r0, 2);
        r1 += __shfl_xor_sync(0xffffffffu, r1, 1);
        r1 += __shfl_xor_sync(0xffffffffu, r1, 2);
        l0 += r0; l1 += r1;

        // P -> smem (per-warp-private rows), tf32
        #pragma unroll
        for (int nt = 0; nt < 8; nt++) {
            uint2 p0 = { f2tf32(s[nt][0]), f2tf32(s[nt][1]) };
            uint2 p1 = { f2tf32(s[nt][2]), f2tf32(s[nt][3]) };
            *(uint2*)(Ps + (w * 16 + g)     * FSTR + nt * 8 + 2 * t) = p0;
            *(uint2*)(Ps + (w * 16 + g + 8) * FSTR + nt * 8 + 2 * t) = p1;
        }
        __syncwarp();

        // O += P * V
        #pragma unroll
        for (int ks = 0; ks < 8; ks++) {
            const int kb = ks * 8;
            const float* ar = Ps + (w * 16 + g) * FSTR + kb;
            const unsigned a0 = __float_as_uint(ar[t]);
            const unsigned a1 = __float_as_uint(ar[8 * FSTR + t]);
            const unsigned a2 = __float_as_uint(ar[t + 4]);
            const unsigned a3 = __float_as_uint(ar[8 * FSTR + t + 4]);
            #pragma unroll
            for (int nt = 0; nt < 8; nt++) {
                const float* br = Vs + (kb + t) * FSTR + nt * 8 + g;
                mma8(o[nt], a0, a1, a2, a3,
                     __float_as_uint(br[0]), __float_as_uint(br[4 * FSTR]));
            }
        }
        __syncwarp();   // Ps reads done before next-iter overwrite
    }

    // normalize + write concat layout [B, N, M]
    const float il0 = 1.0f / l0;
    const float il1 = 1.0f / l1;
    float* Or0 = out + ((size_t)b * NN + qr0) * MM + h * DKK;
    float* Or1 = Or0 + 8 * MM;
    #pragma unroll
    for (int nt = 0; nt < 8; nt++) {
        float2 v0 = { o[nt][0] * il0, o[nt][1] * il0 };
        float2 v1 = { o[nt][2] * il1, o[nt][3] * il1 };
        *(float2*)(Or0 + nt * 8 + 2 * t) = v0;
        *(float2*)(Or1 + nt * 8 + 2 * t) = v1;
    }
}

// ===========================================================================
extern "C" void kernel_launch(void* const* d_in, const int* in_sizes, int n_in,
                              void* d_out, int out_size)
{
    const float* x    = (const float*)d_in[0];
    const float* mask = (const float*)d_in[1];
    const float* Wq   = (const float*)d_in[2];
    const float* bq   = (const float*)d_in[3];
    const float* Wk   = (const float*)d_in[4];
    const float* bk   = (const float*)d_in[5];
    const float* Wv   = (const float*)d_in[6];
    const float* bv   = (const float*)d_in[7];
    const float* Wo   = (const float*)d_in[8];
    const float* bo   = (const float*)d_in[9];
    float* out = (float*)d_out;

    void *pq, *pk, *pv, *pa;
    cudaGetSymbolAddress(&pq, g_q);
    cudaGetSymbolAddress(&pk, g_k);
    cudaGetSymbolAddress(&pv, g_v);
    cudaGetSymbolAddress(&pa, g_att);

    cudaFuncSetAttribute(gemm_mma_kernel,
                         cudaFuncAttributeMaxDynamicSharedMemorySize, GEMM_SMEM);
    cudaFuncSetAttribute(flash_mma_kernel,
                         cudaFuncAttributeMaxDynamicSharedMemorySize, FLASH_SMEM);

    dim3 gemm_grid(MM/128, ROWS/128);  // (8, 32)

    gemm_mma_kernel<<<gemm_grid, 256, GEMM_SMEM>>>(x, Wq, bq, (float*)pq, 1);
    gemm_mma_kernel<<<gemm_grid, 256, GEMM_SMEM>>>(x, Wk, bk, (float*)pk, 1);
    gemm_mma_kernel<<<gemm_grid, 256, GEMM_SMEM>>>(x, Wv, bv, (float*)pv, 1);

    dim3 attn_grid(NN/64, HH, BB);     // (32, 16, 2)
    flash_mma_kernel<<<attn_grid, 128, FLASH_SMEM>>>(mask, (float*)pa);

    gemm_mma_kernel<<<gemm_grid, 256, GEMM_SMEM>>>((const float*)pa, Wo, bo, out, 0);
}

// round 4
// speedup vs baseline: 3.3894x; 1.3201x over previous
#include <cuda_runtime.h>

// Problem constants
#define BB   2
#define NN   2048
#define MM   1024
#define HH   16
#define DKK  64
#define ROWS (BB*NN)   // 4096

// Scratch (allocation-free rule: __device__ globals)
__device__ float g_q[BB*HH*NN*DKK];
__device__ float g_k[BB*HH*NN*DKK];
__device__ float g_v[BB*HH*NN*DKK];
__device__ float g_att[BB*NN*MM];

// ===========================================================================
// Helpers
// ===========================================================================
__device__ __forceinline__ unsigned smem_u32(const void* p) {
    unsigned a;
    asm("{ .reg .u64 t; cvta.to.shared.u64 t, %1; cvt.u32.u64 %0, t; }"
        : "=r"(a) : "l"(p));
    return a;
}
__device__ __forceinline__ unsigned f2tf32(float x) {
    unsigned r;
    asm("cvt.rna.tf32.f32 %0, %1;" : "=r"(r) : "f"(x));
    return r;
}
__device__ __forceinline__ void cp16(unsigned dst, const float* src) {
    asm volatile("cp.async.cg.shared.global [%0], [%1], 16;"
                 :: "r"(dst), "l"(src));
}
#define CP_COMMIT() asm volatile("cp.async.commit_group;" ::: "memory")
#define CP_WAIT1()  asm volatile("cp.async.wait_group 1;" ::: "memory")
#define CP_WAIT0()  asm volatile("cp.async.wait_group 0;" ::: "memory")

// m16n8k8 tf32 MMA. g=lane>>2, t=lane&3.
// A: a0=(g,t) a1=(g+8,t) a2=(g,t+4) a3=(g+8,t+4); B: b0=(k=t,n=g) b1=(k=t+4,n=g)
// C: c0=(g,2t) c1=(g,2t+1) c2=(g+8,2t) c3=(g+8,2t+1)
__device__ __forceinline__ void mma8(float* d, unsigned a0, unsigned a1,
                                     unsigned a2, unsigned a3,
                                     unsigned b0, unsigned b1)
{
    asm("mma.sync.aligned.m16n8k8.row.col.f32.tf32.tf32.f32 "
        "{%0,%1,%2,%3},{%4,%5,%6,%7},{%8,%9},{%0,%1,%2,%3};"
        : "+f"(d[0]), "+f"(d[1]), "+f"(d[2]), "+f"(d[3])
        : "r"(a0), "r"(a1), "r"(a2), "r"(a3), "r"(b0), "r"(b1));
}

// FMA-pipe exp (no MUFU). Valid for x <= 0; ~1e-7 rel accuracy.
__device__ __forceinline__ float fast_exp(float x) {
    float z = fmaxf(x * 1.4426950408889634f, -126.0f);
    float zi = z + 12582912.0f;
    int   n  = __float_as_int(zi);
    float f  = z - (zi - 12582912.0f);
    float p  = 1.33335581e-3f;
    p = p * f + 9.61812911e-3f;
    p = p * f + 5.55041087e-2f;
    p = p * f + 2.40226512e-1f;
    p = p * f + 6.93147182e-1f;
    p = p * f + 1.0f;
    return __int_as_float(__float_as_int(p) + (n << 23));
}

// ===========================================================================
// Tensor-core tf32 GEMM: C[r,c] = sum_k A[r,k]*W[c,k] + bias[c]
// CTA 128x128, 8 warps (2x4), warp tile 64x32, K-chunk 32.
// cp.async double-buffered (raw fp32 in smem, rna cvt at fragment load).
// ===========================================================================
#define GSTR 36
#define GBUF (128*GSTR)          // 4608 floats per operand buffer
#define GEMM_SMEM (4*GBUF*4)     // 73728 bytes

__device__ __forceinline__ void gemm_cp_chunk(
    unsigned sA, unsigned sW,
    const float* __restrict__ A, const float* __restrict__ W,
    int tid, int row0, int col0, int chunk)
{
    #pragma unroll
    for (int k = 0; k < 4; k++) {
        const int u = tid + k * 256;
        const int r = u >> 3;
        const int c = u & 7;
        const unsigned soff = (unsigned)(r * GSTR + c * 4) * 4u;
        cp16(sA + soff, A + (size_t)(row0 + r) * MM + chunk * 32 + c * 4);
        cp16(sW + soff, W + (size_t)(col0 + r) * MM + chunk * 32 + c * 4);
    }
}

__global__ __launch_bounds__(256) void gemm_mma_kernel(
    const float* __restrict__ A, const float* __restrict__ W,
    const float* __restrict__ bias, float* __restrict__ C, int headed)
{
    extern __shared__ float gs[];
    const unsigned sbase = smem_u32(gs);

    const int tid  = threadIdx.x;
    const int w    = tid >> 5;
    const int lane = tid & 31;
    const int g    = lane >> 2;
    const int t    = lane & 3;
    const int row0 = blockIdx.y * 128;
    const int col0 = blockIdx.x * 128;
    const int wm   = (w >> 2) * 64;
    const int wn   = (w & 3) * 32;

    float c[4][4][4] = {};

    // preload chunk 0 into buffer 0
    gemm_cp_chunk(sbase, sbase + 2*GBUF*4u, A, W, tid, row0, col0, 0);
    CP_COMMIT();

    for (int i = 0; i < 32; i++) {
        const int cur = i & 1;
        if (i + 1 < 32) {
            const int nxt = (i + 1) & 1;
            gemm_cp_chunk(sbase + nxt*GBUF*4u, sbase + (2+nxt)*GBUF*4u,
                          A, W, tid, row0, col0, i + 1);
            CP_COMMIT();
            CP_WAIT1();
        } else {
            CP_WAIT0();
        }
        __syncthreads();

        const float* Ab = gs + cur * GBUF;
        const float* Wb = gs + 2*GBUF + cur * GBUF;

        #pragma unroll
        for (int ks = 0; ks < 4; ks++) {
            const int kb = ks * 8;
            unsigned a[4][4];
            #pragma unroll
            for (int mt = 0; mt < 4; mt++) {
                const float* ar = Ab + (wm + mt * 16 + g) * GSTR + kb;
                a[mt][0] = f2tf32(ar[t]);
                a[mt][1] = f2tf32(ar[8 * GSTR + t]);
                a[mt][2] = f2tf32(ar[t + 4]);
                a[mt][3] = f2tf32(ar[8 * GSTR + t + 4]);
            }
            #pragma unroll
            for (int nt = 0; nt < 4; nt++) {
                const float* br = Wb + (wn + nt * 8 + g) * GSTR + kb;
                const unsigned b0 = f2tf32(br[t]);
                const unsigned b1 = f2tf32(br[t + 4]);
                #pragma unroll
                for (int mt = 0; mt < 4; mt++)
                    mma8(c[mt][nt], a[mt][0], a[mt][1], a[mt][2], a[mt][3], b0, b1);
            }
        }
        __syncthreads();   // all warps done with this buffer before re-fill
    }

    // Epilogue
    #pragma unroll
    for (int mt = 0; mt < 4; mt++) {
        const int r0 = row0 + wm + mt * 16 + g;
        const int r1 = r0 + 8;
        #pragma unroll
        for (int nt = 0; nt < 4; nt++) {
            const int col = col0 + wn + nt * 8 + 2 * t;
            const float bx = bias[col], by = bias[col + 1];
            float2 v0 = { c[mt][nt][0] + bx, c[mt][nt][1] + by };
            float2 v1 = { c[mt][nt][2] + bx, c[mt][nt][3] + by };
            if (headed) {
                const int h = col >> 6;
                const int d = col & 63;
                const int b0r = r0 >> 11, n0r = r0 & (NN - 1);
                const int b1r = r1 >> 11, n1r = r1 & (NN - 1);
                *(float2*)(C + (((size_t)(b0r*HH + h))*NN + n0r)*DKK + d) = v0;
                *(float2*)(C + (((size_t)(b1r*HH + h))*NN + n1r)*DKK + d) = v1;
            } else {
                *(float2*)(C + (size_t)r0 * MM + col) = v0;
                *(float2*)(C + (size_t)r1 * MM + col) = v1;
            }
        }
    }
}

// ===========================================================================
// Flash attention, mma.sync tf32.
// CTA = 128 q-rows, 4 warps, warp = 32 rows (2 m-tiles). kv tile 64.
// FSTR=72 (conflict-free for all fragment patterns). K/V cp.async
// double-buffered; P never touches smem (quad-shuffle transpose).
// smem floats: Q[0,9216) K0[9216,13824) K1[13824,18432) V0[18432,23040)
//              V1[23040,27648)  -> 110,592 bytes.
// ===========================================================================
#define FSTR 72
#define FQ_OFF  0
#define FK_OFF  9216
#define FV_OFF  18432
#define FKV     4608                       // 64*72 floats per buffer
#define FLASH_SMEM (27648 * 4)             // 110592 bytes

__device__ __forceinline__ void flash_cp_kv(
    unsigned sK, unsigned sV,
    const float* __restrict__ Kg, const float* __restrict__ Vg,
    int tid, int k0)
{
    #pragma unroll
    for (int j = 0; j < 8; j++) {
        const int u = tid + j * 128;
        const int r = u >> 4;
        const int cc = (u & 15) << 2;
        const unsigned soff = (unsigned)(r * FSTR + cc) * 4u;
        cp16(sK + soff, Kg + (size_t)(k0 + r) * DKK + cc);
        cp16(sV + soff, Vg + (size_t)(k0 + r) * DKK + cc);
    }
}

__global__ __launch_bounds__(128) void flash_mma_kernel(
    const float* __restrict__ mask, float* __restrict__ out)
{
    extern __shared__ float fs[];
    const unsigned sbase = smem_u32(fs);

    const int tid  = threadIdx.x;
    const int w    = tid >> 5;
    const int lane = tid & 31;
    const int g    = lane >> 2;
    const int t    = lane & 3;
    const int q0   = blockIdx.x * 128;
    const int h    = blockIdx.y;
    const int b    = blockIdx.z;

    const float* Qg = g_q + (((size_t)(b*HH + h)) * NN) * DKK;
    const float* Kg = g_k + (((size_t)(b*HH + h)) * NN) * DKK;
    const float* Vg = g_v + (((size_t)(b*HH + h)) * NN) * DKK;
    const float* Mg = mask + (size_t)b * NN * NN;

    // Stage Q (scaled by 0.125, rna tf32) — once.
    for (int u = tid; u < 128 * 16; u += 128) {
        const int r  = u >> 4;
        const int cc = (u & 15) << 2;
        float4 v = *(const float4*)(Qg + (size_t)(q0 + r) * DKK + cc);
        uint4 tv = { f2tf32(v.x * 0.125f), f2tf32(v.y * 0.125f),
                     f2tf32(v.z * 0.125f), f2tf32(v.w * 0.125f) };
        *(uint4*)(fs + FQ_OFF + r * FSTR + cc) = tv;
    }

    // preload kv tile 0 into buffer 0
    flash_cp_kv(sbase + FK_OFF*4u, sbase + FV_OFF*4u, Kg, Vg, tid, 0);
    CP_COMMIT();

    float o[2][8][4] = {};
    float m[2][2] = {{-1e30f,-1e30f},{-1e30f,-1e30f}};
    float l[2][2] = {};

    const int qw = q0 + w * 32;   // warp's first q row

    for (int it = 0; it < 32; it++) {
        const int k0  = it * 64;
        const int cur = it & 1;
        if (it + 1 < 32) {
            const int nxt = (it + 1) & 1;
            flash_cp_kv(sbase + (FK_OFF + nxt*FKV)*4u, sbase + (FV_OFF + nxt*FKV)*4u,
                        Kg, Vg, tid, k0 + 64);
            CP_COMMIT();
            CP_WAIT1();
        } else {
            CP_WAIT0();
        }
        __syncthreads();

        const float* Ks = fs + FK_OFF + cur * FKV;
        const float* Vs = fs + FV_OFF + cur * FKV;

        // ---- S = Q * K^T  (rows qw..qw+31, cols k0..k0+63) ----
        float s[2][8][4] = {};
        #pragma unroll
        for (int ks = 0; ks < 8; ks++) {
            const int kb = ks * 8;
            unsigned aq[2][4];
            #pragma unroll
            for (int mt = 0; mt < 2; mt++) {
                const float* ar = fs + FQ_OFF + (w*32 + mt*16 + g) * FSTR + kb;
                aq[mt][0] = __float_as_uint(ar[t]);
                aq[mt][1] = __float_as_uint(ar[8 * FSTR + t]);
                aq[mt][2] = __float_as_uint(ar[t + 4]);
                aq[mt][3] = __float_as_uint(ar[8 * FSTR + t + 4]);
            }
            #pragma unroll
            for (int nt = 0; nt < 8; nt++) {
                const float* br = Ks + (nt * 8 + g) * FSTR + kb;
                const unsigned b0 = f2tf32(br[t]);
                const unsigned b1 = f2tf32(br[t + 4]);
                mma8(s[0][nt], aq[0][0], aq[0][1], aq[0][2], aq[0][3], b0, b1);
                mma8(s[1][nt], aq[1][0], aq[1][1], aq[1][2], aq[1][3], b0, b1);
            }
        }

        // ---- multiplicative mask ----
        #pragma unroll
        for (int mt = 0; mt < 2; mt++) {
            const float* Mr0 = Mg + (size_t)(qw + mt*16 + g) * NN + k0;
            const float* Mr1 = Mr0 + 8 * NN;
            #pragma unroll
            for (int nt = 0; nt < 8; nt++) {
                float2 ma = *(const float2*)(Mr0 + nt * 8 + 2 * t);
                float2 mb = *(const float2*)(Mr1 + nt * 8 + 2 * t);
                s[mt][nt][0] *= ma.x; s[mt][nt][1] *= ma.y;
                s[mt][nt][2] *= mb.x; s[mt][nt][3] *= mb.y;
            }
        }

        // ---- online softmax (per mt: rows g and g+8; quad = 4 t-lanes) ----
        #pragma unroll
        for (int mt = 0; mt < 2; mt++) {
            float mx0 = -1e30f, mx1 = -1e30f;
            #pragma unroll
            for (int nt = 0; nt < 8; nt++) {
                mx0 = fmaxf(mx0, fmaxf(s[mt][nt][0], s[mt][nt][1]));
                mx1 = fmaxf(mx1, fmaxf(s[mt][nt][2], s[mt][nt][3]));
            }
            mx0 = fmaxf(mx0, __shfl_xor_sync(0xffffffffu, mx0, 1));
            mx0 = fmaxf(mx0, __shfl_xor_sync(0xffffffffu, mx0, 2));
            mx1 = fmaxf(mx1, __shfl_xor_sync(0xffffffffu, mx1, 1));
            mx1 = fmaxf(mx1, __shfl_xor_sync(0xffffffffu, mx1, 2));

            const float mn0 = fmaxf(m[mt][0], mx0);
            const float mn1 = fmaxf(m[mt][1], mx1);
            const float cr0 = fast_exp(m[mt][0] - mn0);
            const float cr1 = fast_exp(m[mt][1] - mn1);
            l[mt][0] *= cr0; l[mt][1] *= cr1;
            m[mt][0] = mn0;  m[mt][1] = mn1;

            float r0 = 0.f, r1 = 0.f;
            #pragma unroll
            for (int nt = 0; nt < 8; nt++) {
                o[mt][nt][0] *= cr0; o[mt][nt][1] *= cr0;
                o[mt][nt][2] *= cr1; o[mt][nt][3] *= cr1;
                s[mt][nt][0] = fast_exp(s[mt][nt][0] - mn0);
                s[mt][nt][1] = fast_exp(s[mt][nt][1] - mn0);
                s[mt][nt][2] = fast_exp(s[mt][nt][2] - mn1);
                s[mt][nt][3] = fast_exp(s[mt][nt][3] - mn1);
                r0 += s[mt][nt][0] + s[mt][nt][1];
                r1 += s[mt][nt][2] + s[mt][nt][3];
            }
            r0 += __shfl_xor_sync(0xffffffffu, r0, 1);
            r0 += __shfl_xor_sync(0xffffffffu, r0, 2);
            r1 += __shfl_xor_sync(0xffffffffu, r1, 1);
            r1 += __shfl_xor_sync(0xffffffffu, r1, 2);
            l[mt][0] += r0; l[mt][1] += r1;
        }

        // ---- O += P * V  (P A-frags via quad-shuffle transpose) ----
        const int halfsrc = t >> 1;
        const bool odd = (t & 1);
        #pragma unroll
        for (int ks = 0; ks < 8; ks++) {
            unsigned a[2][4];
            #pragma unroll
            for (int mt = 0; mt < 2; mt++) {
                float v00 = __shfl_sync(0xffffffffu, s[mt][ks][0], halfsrc, 4);
                float v01 = __shfl_sync(0xffffffffu, s[mt][ks][1], halfsrc, 4);
                float v10 = __shfl_sync(0xffffffffu, s[mt][ks][2], halfsrc, 4);
                float v11 = __shfl_sync(0xffffffffu, s[mt][ks][3], halfsrc, 4);
                float w00 = __shfl_sync(0xffffffffu, s[mt][ks][0], 2 + halfsrc, 4);
                float w01 = __shfl_sync(0xffffffffu, s[mt][ks][1], 2 + halfsrc, 4);
                float w10 = __shfl_sync(0xffffffffu, s[mt][ks][2], 2 + halfsrc, 4);
                float w11 = __shfl_sync(0xffffffffu, s[mt][ks][3], 2 + halfsrc, 4);
                a[mt][0] = f2tf32(odd ? v01 : v00);
                a[mt][1] = f2tf32(odd ? v11 : v10);
                a[mt][2] = f2tf32(odd ? w01 : w00);
                a[mt][3] = f2tf32(odd ? w11 : w10);
            }
            const int kb = ks * 8;
            #pragma unroll
            for (int nt = 0; nt < 8; nt++) {
                const float* br = Vs + (kb + t) * FSTR + nt * 8 + g;
                const unsigned b0 = f2tf32(br[0]);
                const unsigned b1 = f2tf32(br[4 * FSTR]);
                mma8(o[0][nt], a[0][0], a[0][1], a[0][2], a[0][3], b0, b1);
                mma8(o[1][nt], a[1][0], a[1][1], a[1][2], a[1][3], b0, b1);
            }
        }
        __syncthreads();   // all warps done with this buffer before re-fill
    }

    // ---- normalize + write concat layout [B, N, M] ----
    #pragma unroll
    for (int mt = 0; mt < 2; mt++) {
        const float il0 = 1.0f / l[mt][0];
        const float il1 = 1.0f / l[mt][1];
        float* Or0 = out + ((size_t)b * NN + qw + mt*16 + g) * MM + h * DKK;
        float* Or1 = Or0 + 8 * MM;
        #pragma unroll
        for (int nt = 0; nt < 8; nt++) {
            float2 v0 = { o[mt][nt][0] * il0, o[mt][nt][1] * il0 };
            float2 v1 = { o[mt][nt][2] * il1, o[mt][nt][3] * il1 };
            *(float2*)(Or0 + nt * 8 + 2 * t) = v0;
            *(float2*)(Or1 + nt * 8 + 2 * t) = v1;
        }
    }
}

// ===========================================================================
extern "C" void kernel_launch(void* const* d_in, const int* in_sizes, int n_in,
                              void* d_out, int out_size)
{
    const float* x    = (const float*)d_in[0];
    const float* mask = (const float*)d_in[1];
    const float* Wq   = (const float*)d_in[2];
    const float* bq   = (const float*)d_in[3];
    const float* Wk   = (const float*)d_in[4];
    const float* bk   = (const float*)d_in[5];
    const float* Wv   = (const float*)d_in[6];
    const float* bv   = (const float*)d_in[7];
    const float* Wo   = (const float*)d_in[8];
    const float* bo   = (const float*)d_in[9];
    float* out = (float*)d_out;

    void *pq, *pk, *pv, *pa;
    cudaGetSymbolAddress(&pq, g_q);
    cudaGetSymbolAddress(&pk, g_k);
    cudaGetSymbolAddress(&pv, g_v);
    cudaGetSymbolAddress(&pa, g_att);

    cudaFuncSetAttribute(gemm_mma_kernel,
                         cudaFuncAttributeMaxDynamicSharedMemorySize, GEMM_SMEM);
    cudaFuncSetAttribute(flash_mma_kernel,
                         cudaFuncAttributeMaxDynamicSharedMemorySize, FLASH_SMEM);

    dim3 gemm_grid(MM/128, ROWS/128);  // (8, 32)

    gemm_mma_kernel<<<gemm_grid, 256, GEMM_SMEM>>>(x, Wq, bq, (float*)pq, 1);
    gemm_mma_kernel<<<gemm_grid, 256, GEMM_SMEM>>>(x, Wk, bk, (float*)pk, 1);
    gemm_mma_kernel<<<gemm_grid, 256, GEMM_SMEM>>>(x, Wv, bv, (float*)pv, 1);

    dim3 attn_grid(NN/128, HH, BB);    // (16, 16, 2)
    flash_mma_kernel<<<attn_grid, 128, FLASH_SMEM>>>(mask, (float*)pa);

    gemm_mma_kernel<<<gemm_grid, 256, GEMM_SMEM>>>((const float*)pa, Wo, bo, out, 0);
}

// round 5
// speedup vs baseline: 3.9356x; 1.1611x over previous
#include <cuda_runtime.h>

// Problem constants
#define BB   2
#define NN   2048
#define MM   1024
#define HH   16
#define DKK  64
#define ROWS (BB*NN)   // 4096

// Scratch (allocation-free rule: __device__ globals)
__device__ float g_q[BB*HH*NN*DKK];
__device__ float g_k[BB*HH*NN*DKK];
__device__ float g_v[BB*HH*NN*DKK];
__device__ float g_att[BB*NN*MM];

// ===========================================================================
// Helpers
// ===========================================================================
__device__ __forceinline__ unsigned smem_u32(const void* p) {
    unsigned a;
    asm("{ .reg .u64 t; cvta.to.shared.u64 t, %1; cvt.u32.u64 %0, t; }"
        : "=r"(a) : "l"(p));
    return a;
}
__device__ __forceinline__ unsigned f2tf32(float x) {
    unsigned r;
    asm("cvt.rna.tf32.f32 %0, %1;" : "=r"(r) : "f"(x));
    return r;
}
__device__ __forceinline__ float ex2f(float x) {
    float r;
    asm("ex2.approx.f32 %0, %1;" : "=f"(r) : "f"(x));
    return r;
}
__device__ __forceinline__ void cp16(unsigned dst, const float* src) {
    asm volatile("cp.async.cg.shared.global [%0], [%1], 16;"
                 :: "r"(dst), "l"(src));
}
#define CP_COMMIT() asm volatile("cp.async.commit_group;" ::: "memory")
#define CP_WAIT1()  asm volatile("cp.async.wait_group 1;" ::: "memory")
#define CP_WAIT0()  asm volatile("cp.async.wait_group 0;" ::: "memory")

// m16n8k8 tf32 MMA. g=lane>>2, t=lane&3.
// A: a0=(g,t) a1=(g+8,t) a2=(g,t+4) a3=(g+8,t+4); B: b0=(k=t,n=g) b1=(k=t+4,n=g)
// C: c0=(g,2t) c1=(g,2t+1) c2=(g+8,2t) c3=(g+8,2t+1)
__device__ __forceinline__ void mma8(float* d, unsigned a0, unsigned a1,
                                     unsigned a2, unsigned a3,
                                     unsigned b0, unsigned b1)
{
    asm("mma.sync.aligned.m16n8k8.row.col.f32.tf32.tf32.f32 "
        "{%0,%1,%2,%3},{%4,%5,%6,%7},{%8,%9},{%0,%1,%2,%3};"
        : "+f"(d[0]), "+f"(d[1]), "+f"(d[2]), "+f"(d[3])
        : "r"(a0), "r"(a1), "r"(a2), "r"(a3), "r"(b0), "r"(b1));
}

// ===========================================================================
// Tensor-core tf32 GEMM: C[r,c] = sum_k A[r,k]*W[c,k] + bias[c]
// CTA 128x128, 4 warps (2x2), warp tile 64x64, K-chunk 32.
// cp.async double-buffered; rna cvt at fragment load.
// ===========================================================================
#define GSTR 36
#define GBUF (128*GSTR)          // 4608 floats per operand buffer
#define GEMM_SMEM (4*GBUF*4)     // 73728 bytes

__device__ __forceinline__ void gemm_cp_chunk(
    unsigned sA, unsigned sW,
    const float* __restrict__ A, const float* __restrict__ W,
    int tid, int row0, int col0, int chunk)
{
    #pragma unroll
    for (int k = 0; k < 8; k++) {
        const int u = tid + k * 128;
        const int r = u >> 3;
        const int c = u & 7;
        const unsigned soff = (unsigned)(r * GSTR + c * 4) * 4u;
        cp16(sA + soff, A + (size_t)(row0 + r) * MM + chunk * 32 + c * 4);
        cp16(sW + soff, W + (size_t)(col0 + r) * MM + chunk * 32 + c * 4);
    }
}

__global__ __launch_bounds__(128, 2) void gemm_mma_kernel(
    const float* __restrict__ A, const float* __restrict__ W,
    const float* __restrict__ bias, float* __restrict__ C, int headed)
{
    extern __shared__ float gs[];
    const unsigned sbase = smem_u32(gs);

    const int tid  = threadIdx.x;
    const int w    = tid >> 5;
    const int lane = tid & 31;
    const int g    = lane >> 2;
    const int t    = lane & 3;
    const int row0 = blockIdx.y * 128;
    const int col0 = blockIdx.x * 128;
    const int wm   = (w >> 1) * 64;
    const int wn   = (w & 1) * 64;

    float c[4][8][4] = {};

    gemm_cp_chunk(sbase, sbase + 2*GBUF*4u, A, W, tid, row0, col0, 0);
    CP_COMMIT();

    for (int i = 0; i < 32; i++) {
        const int cur = i & 1;
        if (i + 1 < 32) {
            const int nxt = (i + 1) & 1;
            gemm_cp_chunk(sbase + nxt*GBUF*4u, sbase + (2+nxt)*GBUF*4u,
                          A, W, tid, row0, col0, i + 1);
            CP_COMMIT();
            CP_WAIT1();
        } else {
            CP_WAIT0();
        }
        __syncthreads();

        const float* Ab = gs + cur * GBUF;
        const float* Wb = gs + 2*GBUF + cur * GBUF;

        #pragma unroll
        for (int ks = 0; ks < 4; ks++) {
            const int kb = ks * 8;
            unsigned a[4][4];
            #pragma unroll
            for (int mt = 0; mt < 4; mt++) {
                const float* ar = Ab + (wm + mt * 16 + g) * GSTR + kb;
                a[mt][0] = f2tf32(ar[t]);
                a[mt][1] = f2tf32(ar[8 * GSTR + t]);
                a[mt][2] = f2tf32(ar[t + 4]);
                a[mt][3] = f2tf32(ar[8 * GSTR + t + 4]);
            }
            #pragma unroll
            for (int nt = 0; nt < 8; nt++) {
                const float* br = Wb + (wn + nt * 8 + g) * GSTR + kb;
                const unsigned b0 = f2tf32(br[t]);
                const unsigned b1 = f2tf32(br[t + 4]);
                #pragma unroll
                for (int mt = 0; mt < 4; mt++)
                    mma8(c[mt][nt], a[mt][0], a[mt][1], a[mt][2], a[mt][3], b0, b1);
            }
        }
        __syncthreads();
    }

    // Epilogue
    #pragma unroll
    for (int mt = 0; mt < 4; mt++) {
        const int r0 = row0 + wm + mt * 16 + g;
        const int r1 = r0 + 8;
        #pragma unroll
        for (int nt = 0; nt < 8; nt++) {
            const int col = col0 + wn + nt * 8 + 2 * t;
            const float bx = bias[col], by = bias[col + 1];
            float2 v0 = { c[mt][nt][0] + bx, c[mt][nt][1] + by };
            float2 v1 = { c[mt][nt][2] + bx, c[mt][nt][3] + by };
            if (headed) {
                const int h = col >> 6;
                const int d = col & 63;
                const int b0r = r0 >> 11, n0r = r0 & (NN - 1);
                const int b1r = r1 >> 11, n1r = r1 & (NN - 1);
                *(float2*)(C + (((size_t)(b0r*HH + h))*NN + n0r)*DKK + d) = v0;
                *(float2*)(C + (((size_t)(b1r*HH + h))*NN + n1r)*DKK + d) = v1;
            } else {
                *(float2*)(C + (size_t)r0 * MM + col) = v0;
                *(float2*)(C + (size_t)r1 * MM + col) = v1;
            }
        }
    }
}

// ===========================================================================
// Flash attention, mma.sync tf32, NO online softmax (scores are bounded:
// softmax is shift-invariant; direct exp2 cannot overflow here).
// CTA = 128 q-rows, 4 warps, warp = 32 rows. kv tile 64, double-buffered.
// Q staged pre-scaled by 0.125*log2(e) so p = exp2(s*mask).
// FSTR=72: all fragment LDS patterns conflict-free.
// ===========================================================================
#define FSTR 72
#define FQ_OFF  0
#define FK_OFF  9216
#define FV_OFF  18432
#define FKV     4608                       // 64*72 floats per buffer
#define FLASH_SMEM (27648 * 4)             // 110592 bytes

__device__ __forceinline__ void flash_cp_kv(
    unsigned sK, unsigned sV,
    const float* __restrict__ Kg, const float* __restrict__ Vg,
    int tid, int k0)
{
    #pragma unroll
    for (int j = 0; j < 8; j++) {
        const int u = tid + j * 128;
        const int r = u >> 4;
        const int cc = (u & 15) << 2;
        const unsigned soff = (unsigned)(r * FSTR + cc) * 4u;
        cp16(sK + soff, Kg + (size_t)(k0 + r) * DKK + cc);
        cp16(sV + soff, Vg + (size_t)(k0 + r) * DKK + cc);
    }
}

__global__ __launch_bounds__(128, 2) void flash_mma_kernel(
    const float* __restrict__ mask, float* __restrict__ out)
{
    extern __shared__ float fs[];
    const unsigned sbase = smem_u32(fs);

    const int tid  = threadIdx.x;
    const int w    = tid >> 5;
    const int lane = tid & 31;
    const int g    = lane >> 2;
    const int t    = lane & 3;
    const int q0   = blockIdx.x * 128;
    const int h    = blockIdx.y;
    const int b    = blockIdx.z;

    const float* Qg = g_q + (((size_t)(b*HH + h)) * NN) * DKK;
    const float* Kg = g_k + (((size_t)(b*HH + h)) * NN) * DKK;
    const float* Vg = g_v + (((size_t)(b*HH + h)) * NN) * DKK;
    const float* Mg = mask + (size_t)b * NN * NN;

    // Stage Q, scaled by 0.125*log2(e), rna tf32 — once.
    const float qscale = 0.125f * 1.4426950408889634f;
    for (int u = tid; u < 128 * 16; u += 128) {
        const int r  = u >> 4;
        const int cc = (u & 15) << 2;
        float4 v = *(const float4*)(Qg + (size_t)(q0 + r) * DKK + cc);
        uint4 tv = { f2tf32(v.x * qscale), f2tf32(v.y * qscale),
                     f2tf32(v.z * qscale), f2tf32(v.w * qscale) };
        *(uint4*)(fs + FQ_OFF + r * FSTR + cc) = tv;
    }

    flash_cp_kv(sbase + FK_OFF*4u, sbase + FV_OFF*4u, Kg, Vg, tid, 0);
    CP_COMMIT();

    float o[2][8][4] = {};
    float lacc[2][2] = {};

    const int qw = q0 + w * 32;

    for (int it = 0; it < 32; it++) {
        const int k0  = it * 64;
        const int cur = it & 1;
        if (it + 1 < 32) {
            const int nxt = (it + 1) & 1;
            flash_cp_kv(sbase + (FK_OFF + nxt*FKV)*4u, sbase + (FV_OFF + nxt*FKV)*4u,
                        Kg, Vg, tid, k0 + 64);
            CP_COMMIT();
            CP_WAIT1();
        } else {
            CP_WAIT0();
        }
        __syncthreads();

        const float* Ks = fs + FK_OFF + cur * FKV;
        const float* Vs = fs + FV_OFF + cur * FKV;

        // ---- S~ = (Q*log2e/8) * K^T ----
        float s[2][8][4] = {};
        #pragma unroll
        for (int ks = 0; ks < 8; ks++) {
            const int kb = ks * 8;
            unsigned aq[2][4];
            #pragma unroll
            for (int mt = 0; mt < 2; mt++) {
                const float* ar = fs + FQ_OFF + (w*32 + mt*16 + g) * FSTR + kb;
                aq[mt][0] = __float_as_uint(ar[t]);
                aq[mt][1] = __float_as_uint(ar[8 * FSTR + t]);
                aq[mt][2] = __float_as_uint(ar[t + 4]);
                aq[mt][3] = __float_as_uint(ar[8 * FSTR + t + 4]);
            }
            #pragma unroll
            for (int nt = 0; nt < 8; nt++) {
                const float* br = Ks + (nt * 8 + g) * FSTR + kb;
                const unsigned b0 = f2tf32(br[t]);
                const unsigned b1 = f2tf32(br[t + 4]);
                mma8(s[0][nt], aq[0][0], aq[0][1], aq[0][2], aq[0][3], b0, b1);
                mma8(s[1][nt], aq[1][0], aq[1][1], aq[1][2], aq[1][3], b0, b1);
            }
        }

        // ---- p = exp2(s~ * mask); accumulate per-thread row sums ----
        #pragma unroll
        for (int mt = 0; mt < 2; mt++) {
            const float* Mr0 = Mg + (size_t)(qw + mt*16 + g) * NN + k0;
            const float* Mr1 = Mr0 + 8 * NN;
            float r0 = 0.f, r1 = 0.f;
            #pragma unroll
            for (int nt = 0; nt < 8; nt++) {
                float2 ma = *(const float2*)(Mr0 + nt * 8 + 2 * t);
                float2 mb = *(const float2*)(Mr1 + nt * 8 + 2 * t);
                s[mt][nt][0] = ex2f(s[mt][nt][0] * ma.x);
                s[mt][nt][1] = ex2f(s[mt][nt][1] * ma.y);
                s[mt][nt][2] = ex2f(s[mt][nt][2] * mb.x);
                s[mt][nt][3] = ex2f(s[mt][nt][3] * mb.y);
                r0 += s[mt][nt][0] + s[mt][nt][1];
                r1 += s[mt][nt][2] + s[mt][nt][3];
            }
            lacc[mt][0] += r0;
            lacc[mt][1] += r1;
        }

        // ---- O += P * V  (P A-frags via quad-shuffle transpose) ----
        const int halfsrc = t >> 1;
        const bool odd = (t & 1);
        #pragma unroll
        for (int ks = 0; ks < 8; ks++) {
            unsigned a[2][4];
            #pragma unroll
            for (int mt = 0; mt < 2; mt++) {
                float v00 = __shfl_sync(0xffffffffu, s[mt][ks][0], halfsrc, 4);
                float v01 = __shfl_sync(0xffffffffu, s[mt][ks][1], halfsrc, 4);
                float v10 = __shfl_sync(0xffffffffu, s[mt][ks][2], halfsrc, 4);
                float v11 = __shfl_sync(0xffffffffu, s[mt][ks][3], halfsrc, 4);
                float w00 = __shfl_sync(0xffffffffu, s[mt][ks][0], 2 + halfsrc, 4);
                float w01 = __shfl_sync(0xffffffffu, s[mt][ks][1], 2 + halfsrc, 4);
                float w10 = __shfl_sync(0xffffffffu, s[mt][ks][2], 2 + halfsrc, 4);
                float w11 = __shfl_sync(0xffffffffu, s[mt][ks][3], 2 + halfsrc, 4);
                a[mt][0] = f2tf32(odd ? v01 : v00);
                a[mt][1] = f2tf32(odd ? v11 : v10);
                a[mt][2] = f2tf32(odd ? w01 : w00);
                a[mt][3] = f2tf32(odd ? w11 : w10);
            }
            const int kb = ks * 8;
            #pragma unroll
            for (int nt = 0; nt < 8; nt++) {
                const float* br = Vs + (kb + t) * FSTR + nt * 8 + g;
                const unsigned b0 = f2tf32(br[0]);
                const unsigned b1 = f2tf32(br[4 * FSTR]);
                mma8(o[0][nt], a[0][0], a[0][1], a[0][2], a[0][3], b0, b1);
                mma8(o[1][nt], a[1][0], a[1][1], a[1][2], a[1][3], b0, b1);
            }
        }
        __syncthreads();
    }

    // ---- final l reduction (once) + normalize + write concat [B,N,M] ----
    #pragma unroll
    for (int mt = 0; mt < 2; mt++) {
        float l0 = lacc[mt][0], l1 = lacc[mt][1];
        l0 += __shfl_xor_sync(0xffffffffu, l0, 1);
        l0 += __shfl_xor_sync(0xffffffffu, l0, 2);
        l1 += __shfl_xor_sync(0xffffffffu, l1, 1);
        l1 += __shfl_xor_sync(0xffffffffu, l1, 2);
        const float il0 = 1.0f / l0;
        const float il1 = 1.0f / l1;
        float* Or0 = out + ((size_t)b * NN + qw + mt*16 + g) * MM + h * DKK;
        float* Or1 = Or0 + 8 * MM;
        #pragma unroll
        for (int nt = 0; nt < 8; nt++) {
            float2 v0 = { o[mt][nt][0] * il0, o[mt][nt][1] * il0 };
            float2 v1 = { o[mt][nt][2] * il1, o[mt][nt][3] * il1 };
            *(float2*)(Or0 + nt * 8 + 2 * t) = v0;
            *(float2*)(Or1 + nt * 8 + 2 * t) = v1;
        }
    }
}

// ===========================================================================
extern "C" void kernel_launch(void* const* d_in, const int* in_sizes, int n_in,
                              void* d_out, int out_size)
{
    const float* x    = (const float*)d_in[0];
    const float* mask = (const float*)d_in[1];
    const float* Wq   = (const float*)d_in[2];
    const float* bq   = (const float*)d_in[3];
    const float* Wk   = (const float*)d_in[4];
    const float* bk   = (const float*)d_in[5];
    const float* Wv   = (const float*)d_in[6];
    const float* bv   = (const float*)d_in[7];
    const float* Wo   = (const float*)d_in[8];
    const float* bo   = (const float*)d_in[9];
    float* out = (float*)d_out;

    void *pq, *pk, *pv, *pa;
    cudaGetSymbolAddress(&pq, g_q);
    cudaGetSymbolAddress(&pk, g_k);
    cudaGetSymbolAddress(&pv, g_v);
    cudaGetSymbolAddress(&pa, g_att);

    cudaFuncSetAttribute(gemm_mma_kernel,
                         cudaFuncAttributeMaxDynamicSharedMemorySize, GEMM_SMEM);
    cudaFuncSetAttribute(flash_mma_kernel,
                         cudaFuncAttributeMaxDynamicSharedMemorySize, FLASH_SMEM);

    dim3 gemm_grid(MM/128, ROWS/128);  // (8, 32)

    gemm_mma_kernel<<<gemm_grid, 128, GEMM_SMEM>>>(x, Wq, bq, (float*)pq, 1);
    gemm_mma_kernel<<<gemm_grid, 128, GEMM_SMEM>>>(x, Wk, bk, (float*)pk, 1);
    gemm_mma_kernel<<<gemm_grid, 128, GEMM_SMEM>>>(x, Wv, bv, (float*)pv, 1);

    dim3 attn_grid(NN/128, HH, BB);    // (16, 16, 2)
    flash_mma_kernel<<<attn_grid, 128, FLASH_SMEM>>>(mask, (float*)pa);

    gemm_mma_kernel<<<gemm_grid, 128, GEMM_SMEM>>>((const float*)pa, Wo, bo, out, 0);
}

// round 6
// speedup vs baseline: 4.1280x; 1.0489x over previous
#include <cuda_runtime.h>

// Problem constants
#define BB   2
#define NN   2048
#define MM   1024
#define HH   16
#define DKK  64
#define ROWS (BB*NN)   // 4096

// Scratch (allocation-free rule: __device__ globals)
__device__ float g_q[BB*HH*NN*DKK];
__device__ float g_k[BB*HH*NN*DKK];
__device__ float g_v[BB*HH*NN*DKK];
__device__ float g_att[BB*NN*MM];
__device__ float g_xt[ROWS*MM];        // tf32-rounded x
__device__ float g_wt[4*MM*MM];        // tf32-rounded Wq,Wk,Wv,Wo

// ===========================================================================
// Helpers
// ===========================================================================
__device__ __forceinline__ unsigned smem_u32(const void* p) {
    unsigned a;
    asm("{ .reg .u64 t; cvta.to.shared.u64 t, %1; cvt.u32.u64 %0, t; }"
        : "=r"(a) : "l"(p));
    return a;
}
__device__ __forceinline__ unsigned f2tf32(float x) {
    unsigned r;
    asm("cvt.rna.tf32.f32 %0, %1;" : "=r"(r) : "f"(x));
    return r;
}
__device__ __forceinline__ float ex2f(float x) {
    float r;
    asm("ex2.approx.f32 %0, %1;" : "=f"(r) : "f"(x));
    return r;
}
__device__ __forceinline__ void cp16(unsigned dst, const float* src) {
    asm volatile("cp.async.cg.shared.global [%0], [%1], 16;"
                 :: "r"(dst), "l"(src));
}
#define CP_COMMIT() asm volatile("cp.async.commit_group;" ::: "memory")
#define CP_WAIT1()  asm volatile("cp.async.wait_group 1;" ::: "memory")
#define CP_WAIT0()  asm volatile("cp.async.wait_group 0;" ::: "memory")

// m16n8k8 tf32 MMA. g=lane>>2, t=lane&3.
// A: a0=(g,t) a1=(g+8,t) a2=(g,t+4) a3=(g+8,t+4); B: b0=(k=t,n=g) b1=(k=t+4,n=g)
// C: c0=(g,2t) c1=(g,2t+1) c2=(g+8,2t) c3=(g+8,2t+1)
__device__ __forceinline__ void mma8(float* d, unsigned a0, unsigned a1,
                                     unsigned a2, unsigned a3,
                                     unsigned b0, unsigned b1)
{
    asm("mma.sync.aligned.m16n8k8.row.col.f32.tf32.tf32.f32 "
        "{%0,%1,%2,%3},{%4,%5,%6,%7},{%8,%9},{%0,%1,%2,%3};"
        : "+f"(d[0]), "+f"(d[1]), "+f"(d[2]), "+f"(d[3])
        : "r"(a0), "r"(a1), "r"(a2), "r"(a3), "r"(b0), "r"(b1));
}

// ===========================================================================
// Prep: round fp32 -> tf32 bits (rna), elementwise float4
// ===========================================================================
__global__ __launch_bounds__(256) void round_tf32_kernel(
    const float* __restrict__ src, float* __restrict__ dst, int n4)
{
    const int i = blockIdx.x * blockDim.x + threadIdx.x;
    if (i < n4) {
        float4 v = ((const float4*)src)[i];
        uint4 t = { f2tf32(v.x), f2tf32(v.y), f2tf32(v.z), f2tf32(v.w) };
        ((uint4*)dst)[i] = t;
    }
}

// ===========================================================================
// Tensor-core tf32 GEMM body: C[r,c] = sum_k A[r,k]*W[c,k] + bias[c]
// A and W MUST be pre-rounded tf32 (plain fragment loads, no cvt).
// CTA 128x128, 4 warps, warp tile 64x64, K-chunk 32, cp.async double buffer.
// HEADED=1: scatter to [B,H,N,DK], store tf32-rounded.
// HEADED=0: flat [ROWS,MM], store full fp32.
// ===========================================================================
#define GSTR 36
#define GBUF (128*GSTR)          // 4608 floats per operand buffer
#define GEMM_SMEM (4*GBUF*4)     // 73728 bytes

__device__ __forceinline__ void gemm_cp_chunk(
    unsigned sA, unsigned sW,
    const float* __restrict__ A, const float* __restrict__ W,
    int tid, int row0, int col0, int chunk)
{
    #pragma unroll
    for (int k = 0; k < 8; k++) {
        const int u = tid + k * 128;
        const int r = u >> 3;
        const int c = u & 7;
        const unsigned soff = (unsigned)(r * GSTR + c * 4) * 4u;
        cp16(sA + soff, A + (size_t)(row0 + r) * MM + chunk * 32 + c * 4);
        cp16(sW + soff, W + (size_t)(col0 + r) * MM + chunk * 32 + c * 4);
    }
}

template<int HEADED>
__device__ __forceinline__ void gemm_body(
    const float* __restrict__ A, const float* __restrict__ W,
    const float* __restrict__ bias, float* __restrict__ C)
{
    extern __shared__ float gs[];
    const unsigned sbase = smem_u32(gs);

    const int tid  = threadIdx.x;
    const int w    = tid >> 5;
    const int lane = tid & 31;
    const int g    = lane >> 2;
    const int t    = lane & 3;
    const int row0 = blockIdx.y * 128;
    const int col0 = blockIdx.x * 128;
    const int wm   = (w >> 1) * 64;
    const int wn   = (w & 1) * 64;

    float c[4][8][4] = {};

    gemm_cp_chunk(sbase, sbase + 2*GBUF*4u, A, W, tid, row0, col0, 0);
    CP_COMMIT();

    for (int i = 0; i < 32; i++) {
        const int cur = i & 1;
        if (i + 1 < 32) {
            const int nxt = (i + 1) & 1;
            gemm_cp_chunk(sbase + nxt*GBUF*4u, sbase + (2+nxt)*GBUF*4u,
                          A, W, tid, row0, col0, i + 1);
            CP_COMMIT();
            CP_WAIT1();
        } else {
            CP_WAIT0();
        }
        __syncthreads();

        const float* Ab = gs + cur * GBUF;
        const float* Wb = gs + 2*GBUF + cur * GBUF;

        #pragma unroll
        for (int ks = 0; ks < 4; ks++) {
            const int kb = ks * 8;
            unsigned a[4][4];
            #pragma unroll
            for (int mt = 0; mt < 4; mt++) {
                const float* ar = Ab + (wm + mt * 16 + g) * GSTR + kb;
                a[mt][0] = __float_as_uint(ar[t]);
                a[mt][1] = __float_as_uint(ar[8 * GSTR + t]);
                a[mt][2] = __float_as_uint(ar[t + 4]);
                a[mt][3] = __float_as_uint(ar[8 * GSTR + t + 4]);
            }
            #pragma unroll
            for (int nt = 0; nt < 8; nt++) {
                const float* br = Wb + (wn + nt * 8 + g) * GSTR + kb;
                const unsigned b0 = __float_as_uint(br[t]);
                const unsigned b1 = __float_as_uint(br[t + 4]);
                #pragma unroll
                for (int mt = 0; mt < 4; mt++)
                    mma8(c[mt][nt], a[mt][0], a[mt][1], a[mt][2], a[mt][3], b0, b1);
            }
        }
        __syncthreads();
    }

    // Epilogue
    #pragma unroll
    for (int mt = 0; mt < 4; mt++) {
        const int r0 = row0 + wm + mt * 16 + g;
        const int r1 = r0 + 8;
        #pragma unroll
        for (int nt = 0; nt < 8; nt++) {
            const int col = col0 + wn + nt * 8 + 2 * t;
            const float bx = bias[col], by = bias[col + 1];
            float2 v0 = { c[mt][nt][0] + bx, c[mt][nt][1] + by };
            float2 v1 = { c[mt][nt][2] + bx, c[mt][nt][3] + by };
            if (HEADED) {
                v0.x = __uint_as_float(f2tf32(v0.x));
                v0.y = __uint_as_float(f2tf32(v0.y));
                v1.x = __uint_as_float(f2tf32(v1.x));
                v1.y = __uint_as_float(f2tf32(v1.y));
                const int h = col >> 6;
                const int d = col & 63;
                const int b0r = r0 >> 11, n0r = r0 & (NN - 1);
                const int b1r = r1 >> 11, n1r = r1 & (NN - 1);
                *(float2*)(C + (((size_t)(b0r*HH + h))*NN + n0r)*DKK + d) = v0;
                *(float2*)(C + (((size_t)(b1r*HH + h))*NN + n1r)*DKK + d) = v1;
            } else {
                *(float2*)(C + (size_t)r0 * MM + col) = v0;
                *(float2*)(C + (size_t)r1 * MM + col) = v1;
            }
        }
    }
}

// Fused Q/K/V projections: blockIdx.z selects weight/bias/dest.
__global__ __launch_bounds__(128, 2) void qkv_mma_kernel(
    const float* __restrict__ A, const float* __restrict__ Wt,
    const float* __restrict__ bq, const float* __restrict__ bk,
    const float* __restrict__ bv,
    float* __restrict__ dq, float* __restrict__ dk, float* __restrict__ dv)
{
    const int z = blockIdx.z;
    const float* W    = Wt + (size_t)z * MM * MM;
    const float* bias = (z == 0) ? bq : (z == 1) ? bk : bv;
    float*       C    = (z == 0) ? dq : (z == 1) ? dk : dv;
    gemm_body<1>(A, W, bias, C);
}

__global__ __launch_bounds__(128, 2) void out_mma_kernel(
    const float* __restrict__ A, const float* __restrict__ W,
    const float* __restrict__ bias, float* __restrict__ C)
{
    gemm_body<0>(A, W, bias, C);
}

// ===========================================================================
// Flash attention, mma.sync tf32, no online softmax (bounded scores).
// CTA = 128 q-rows, 4 warps, warp = 32 rows. kv tile 64, double-buffered.
// K/V arrive pre-rounded tf32 -> plain fragment loads.
// Row sums of P computed by the tensor pipe via a ones-column in V padding.
// FSTR=72: conflict-free fragment LDS; V cols 64..71 = {1,0,...,0}.
// ===========================================================================
#define FSTR 72
#define FQ_OFF  0
#define FK_OFF  9216
#define FV_OFF  18432
#define FKV     4608                       // 64*72 floats per buffer
#define FLASH_SMEM (27648 * 4)             // 110592 bytes

__device__ __forceinline__ void flash_cp_kv(
    unsigned sK, unsigned sV,
    const float* __restrict__ Kg, const float* __restrict__ Vg,
    int tid, int k0)
{
    #pragma unroll
    for (int j = 0; j < 8; j++) {
        const int u = tid + j * 128;
        const int r = u >> 4;
        const int cc = (u & 15) << 2;
        const unsigned soff = (unsigned)(r * FSTR + cc) * 4u;
        cp16(sK + soff, Kg + (size_t)(k0 + r) * DKK + cc);
        cp16(sV + soff, Vg + (size_t)(k0 + r) * DKK + cc);
    }
}

__global__ __launch_bounds__(128, 2) void flash_mma_kernel(
    const float* __restrict__ mask, float* __restrict__ out)
{
    extern __shared__ float fs[];
    const unsigned sbase = smem_u32(fs);

    const int tid  = threadIdx.x;
    const int w    = tid >> 5;
    const int lane = tid & 31;
    const int g    = lane >> 2;
    const int t    = lane & 3;
    const int q0   = blockIdx.x * 128;
    const int h    = blockIdx.y;
    const int b    = blockIdx.z;

    const float* Qg = g_q + (((size_t)(b*HH + h)) * NN) * DKK;
    const float* Kg = g_k + (((size_t)(b*HH + h)) * NN) * DKK;
    const float* Vg = g_v + (((size_t)(b*HH + h)) * NN) * DKK;
    const float* Mg = mask + (size_t)b * NN * NN;

    // Stage Q, scaled by 0.125*log2(e), rna tf32 — once.
    const float qscale = 0.125f * 1.4426950408889634f;
    for (int u = tid; u < 128 * 16; u += 128) {
        const int r  = u >> 4;
        const int cc = (u & 15) << 2;
        float4 v = *(const float4*)(Qg + (size_t)(q0 + r) * DKK + cc);
        uint4 tv = { f2tf32(v.x * qscale), f2tf32(v.y * qscale),
                     f2tf32(v.z * qscale), f2tf32(v.w * qscale) };
        *(uint4*)(fs + FQ_OFF + r * FSTR + cc) = tv;
    }

    // Init V padding cols: col 64 = 1.0 (ones column), 65..71 = 0. Both buffers.
    for (int u = tid; u < 128; u += 128) {
        float* vrow = fs + FV_OFF + (u >> 6) * FKV + (u & 63) * FSTR;
        vrow[64] = 1.0f;
        vrow[65] = 0.f; vrow[66] = 0.f; vrow[67] = 0.f;
        vrow[68] = 0.f; vrow[69] = 0.f; vrow[70] = 0.f; vrow[71] = 0.f;
    }

    flash_cp_kv(sbase + FK_OFF*4u, sbase + FV_OFF*4u, Kg, Vg, tid, 0);
    CP_COMMIT();

    float o[2][8][4] = {};
    float ol[2][4] = {};      // ones-column accum: c0 = rowsum(g), c2 = rowsum(g+8)

    const int qw = q0 + w * 32;

    for (int it = 0; it < 32; it++) {
        const int k0  = it * 64;
        const int cur = it & 1;
        if (it + 1 < 32) {
            const int nxt = (it + 1) & 1;
            flash_cp_kv(sbase + (FK_OFF + nxt*FKV)*4u, sbase + (FV_OFF + nxt*FKV)*4u,
                        Kg, Vg, tid, k0 + 64);
            CP_COMMIT();
            CP_WAIT1();
        } else {
            CP_WAIT0();
        }
        __syncthreads();

        const float* Ks = fs + FK_OFF + cur * FKV;
        const float* Vs = fs + FV_OFF + cur * FKV;

        // ---- S~ = (Q*log2e/8) * K^T ----
        float s[2][8][4] = {};
        #pragma unroll
        for (int ks = 0; ks < 8; ks++) {
            const int kb = ks * 8;
            unsigned aq[2][4];
            #pragma unroll
            for (int mt = 0; mt < 2; mt++) {
                const float* ar = fs + FQ_OFF + (w*32 + mt*16 + g) * FSTR + kb;
                aq[mt][0] = __float_as_uint(ar[t]);
                aq[mt][1] = __float_as_uint(ar[8 * FSTR + t]);
                aq[mt][2] = __float_as_uint(ar[t + 4]);
                aq[mt][3] = __float_as_uint(ar[8 * FSTR + t + 4]);
            }
            #pragma unroll
            for (int nt = 0; nt < 8; nt++) {
                const float* br = Ks + (nt * 8 + g) * FSTR + kb;
                const unsigned b0 = __float_as_uint(br[t]);
                const unsigned b1 = __float_as_uint(br[t + 4]);
                mma8(s[0][nt], aq[0][0], aq[0][1], aq[0][2], aq[0][3], b0, b1);
                mma8(s[1][nt], aq[1][0], aq[1][1], aq[1][2], aq[1][3], b0, b1);
            }
        }

        // ---- p = exp2(s~ * mask) ----
        #pragma unroll
        for (int mt = 0; mt < 2; mt++) {
            const float* Mr0 = Mg + (size_t)(qw + mt*16 + g) * NN + k0;
            const float* Mr1 = Mr0 + 8 * NN;
            #pragma unroll
            for (int nt = 0; nt < 8; nt++) {
                float2 ma = *(const float2*)(Mr0 + nt * 8 + 2 * t);
                float2 mb = *(const float2*)(Mr1 + nt * 8 + 2 * t);
                s[mt][nt][0] = ex2f(s[mt][nt][0] * ma.x);
                s[mt][nt][1] = ex2f(s[mt][nt][1] * ma.y);
                s[mt][nt][2] = ex2f(s[mt][nt][2] * mb.x);
                s[mt][nt][3] = ex2f(s[mt][nt][3] * mb.y);
            }
        }

        // ---- O += P * V ; rowsum via ones column ----
        const int halfsrc = t >> 1;
        const bool odd = (t & 1);
        #pragma unroll
        for (int ks = 0; ks < 8; ks++) {
            unsigned a[2][4];
            #pragma unroll
            for (int mt = 0; mt < 2; mt++) {
                float v00 = __shfl_sync(0xffffffffu, s[mt][ks][0], halfsrc, 4);
                float v01 = __shfl_sync(0xffffffffu, s[mt][ks][1], halfsrc, 4);
                float v10 = __shfl_sync(0xffffffffu, s[mt][ks][2], halfsrc, 4);
                float v11 = __shfl_sync(0xffffffffu, s[mt][ks][3], halfsrc, 4);
                float w00 = __shfl_sync(0xffffffffu, s[mt][ks][0], 2 + halfsrc, 4);
                float w01 = __shfl_sync(0xffffffffu, s[mt][ks][1], 2 + halfsrc, 4);
                float w10 = __shfl_sync(0xffffffffu, s[mt][ks][2], 2 + halfsrc, 4);
                float w11 = __shfl_sync(0xffffffffu, s[mt][ks][3], 2 + halfsrc, 4);
                a[mt][0] = f2tf32(odd ? v01 : v00);
                a[mt][1] = f2tf32(odd ? v11 : v10);
                a[mt][2] = f2tf32(odd ? w01 : w00);
                a[mt][3] = f2tf32(odd ? w11 : w10);
            }
            const int kb = ks * 8;
            #pragma unroll
            for (int nt = 0; nt < 8; nt++) {
                const float* br = Vs + (kb + t) * FSTR + nt * 8 + g;
                const unsigned b0 = __float_as_uint(br[0]);
                const unsigned b1 = __float_as_uint(br[4 * FSTR]);
                mma8(o[0][nt], a[0][0], a[0][1], a[0][2], a[0][3], b0, b1);
                mma8(o[1][nt], a[1][0], a[1][1], a[1][2], a[1][3], b0, b1);
            }
            // ones column (V cols 64..71: {1,0,...})
            {
                const float* br = Vs + (kb + t) * FSTR + 64 + g;
                const unsigned b0 = __float_as_uint(br[0]);
                const unsigned b1 = __float_as_uint(br[4 * FSTR]);
                mma8(ol[0], a[0][0], a[0][1], a[0][2], a[0][3], b0, b1);
                mma8(ol[1], a[1][0], a[1][1], a[1][2], a[1][3], b0, b1);
            }
        }
        __syncthreads();
    }

    // ---- l broadcast (rowsum lives at quad lane t=0: c0=row g, c2=row g+8) ----
    #pragma unroll
    for (int mt = 0; mt < 2; mt++) {
        const float l0 = __shfl_sync(0xffffffffu, ol[mt][0], lane & 28);
        const float l1 = __shfl_sync(0xffffffffu, ol[mt][2], lane & 28);
        const float il0 = 1.0f / l0;
        const float il1 = 1.0f / l1;
        float* Or0 = out + ((size_t)b * NN + qw + mt*16 + g) * MM + h * DKK;
        float* Or1 = Or0 + 8 * MM;
        #pragma unroll
        for (int nt = 0; nt < 8; nt++) {
            float2 v0 = { __uint_as_float(f2tf32(o[mt][nt][0] * il0)),
                          __uint_as_float(f2tf32(o[mt][nt][1] * il0)) };
            float2 v1 = { __uint_as_float(f2tf32(o[mt][nt][2] * il1)),
                          __uint_as_float(f2tf32(o[mt][nt][3] * il1)) };
            *(float2*)(Or0 + nt * 8 + 2 * t) = v0;
            *(float2*)(Or1 + nt * 8 + 2 * t) = v1;
        }
    }
}

// ===========================================================================
extern "C" void kernel_launch(void* const* d_in, const int* in_sizes, int n_in,
                              void* d_out, int out_size)
{
    const float* x    = (const float*)d_in[0];
    const float* mask = (const float*)d_in[1];
    const float* Wq   = (const float*)d_in[2];
    const float* bq   = (const float*)d_in[3];
    const float* Wk   = (const float*)d_in[4];
    const float* bk   = (const float*)d_in[5];
    const float* Wv   = (const float*)d_in[6];
    const float* bv   = (const float*)d_in[7];
    const float* Wo   = (const float*)d_in[8];
    const float* bo   = (const float*)d_in[9];
    float* out = (float*)d_out;

    void *pq, *pk, *pv, *pa, *pxt, *pwt;
    cudaGetSymbolAddress(&pq,  g_q);
    cudaGetSymbolAddress(&pk,  g_k);
    cudaGetSymbolAddress(&pv,  g_v);
    cudaGetSymbolAddress(&pa,  g_att);
    cudaGetSymbolAddress(&pxt, g_xt);
    cudaGetSymbolAddress(&pwt, g_wt);

    float* xt = (float*)pxt;
    float* wt = (float*)pwt;

    cudaFuncSetAttribute(qkv_mma_kernel,
                         cudaFuncAttributeMaxDynamicSharedMemorySize, GEMM_SMEM);
    cudaFuncSetAttribute(out_mma_kernel,
                         cudaFuncAttributeMaxDynamicSharedMemorySize, GEMM_SMEM);
    cudaFuncSetAttribute(flash_mma_kernel,
                         cudaFuncAttributeMaxDynamicSharedMemorySize, FLASH_SMEM);

    // Pre-round operands to tf32 (rna) once.
    round_tf32_kernel<<<(ROWS*MM/4 + 255)/256, 256>>>(x,  xt, ROWS*MM/4);
    round_tf32_kernel<<<(MM*MM/4 + 255)/256, 256>>>(Wq, wt + 0*MM*MM, MM*MM/4);
    round_tf32_kernel<<<(MM*MM/4 + 255)/256, 256>>>(Wk, wt + 1*MM*MM, MM*MM/4);
    round_tf32_kernel<<<(MM*MM/4 + 255)/256, 256>>>(Wv, wt + 2*MM*MM, MM*MM/4);
    round_tf32_kernel<<<(MM*MM/4 + 255)/256, 256>>>(Wo, wt + 3*MM*MM, MM*MM/4);

    // Fused Q/K/V projections
    dim3 qkv_grid(MM/128, ROWS/128, 3);   // (8, 32, 3)
    qkv_mma_kernel<<<qkv_grid, 128, GEMM_SMEM>>>(
        xt, wt, bq, bk, bv, (float*)pq, (float*)pk, (float*)pv);

    // Fused attention
    dim3 attn_grid(NN/128, HH, BB);       // (16, 16, 2)
    flash_mma_kernel<<<attn_grid, 128, FLASH_SMEM>>>(mask, (float*)pa);

    // Output projection
    dim3 out_grid(MM/128, ROWS/128);      // (8, 32)
    out_mma_kernel<<<out_grid, 128, GEMM_SMEM>>>((const float*)pa, wt + 3*MM*MM, bo, out);
}

// round 8
// speedup vs baseline: 4.5837x; 1.1104x over previous
#include <cuda_runtime.h>
#include <cuda_fp16.h>

// Problem constants
#define BB   2
#define NN   2048
#define MM   1024
#define HH   16
#define DKK  64
#define ROWS (BB*NN)   // 4096

// Scratch (allocation-free rule: __device__ globals)
__device__ float g_q[BB*HH*NN*DKK];
__device__ float g_k[BB*HH*NN*DKK];
__device__ float g_v[BB*HH*NN*DKK];
__device__ float g_att[BB*NN*MM];
__device__ float g_xt[ROWS*MM];                 // tf32-rounded x
__device__ float g_wt[4*MM*MM];                 // tf32-rounded Wq,Wk,Wv,Wo
__device__ __half g_vt[BB*HH*DKK*NN];           // V transposed, fp16

// ===========================================================================
// Helpers
// ===========================================================================
__device__ __forceinline__ unsigned smem_u32(const void* p) {
    unsigned a;
    asm("{ .reg .u64 t; cvta.to.shared.u64 t, %1; cvt.u32.u64 %0, t; }"
        : "=r"(a) : "l"(p));
    return a;
}
__device__ __forceinline__ unsigned f2tf32(float x) {
    unsigned r;
    asm("cvt.rna.tf32.f32 %0, %1;" : "=r"(r) : "f"(x));
    return r;
}
__device__ __forceinline__ float ex2f(float x) {
    float r;
    asm("ex2.approx.f32 %0, %1;" : "=f"(r) : "f"(x));
    return r;
}
__device__ __forceinline__ unsigned pack_f16(float lo, float hi) {
    unsigned r;
    asm("cvt.rn.f16x2.f32 %0, %1, %2;" : "=r"(r) : "f"(hi), "f"(lo));
    return r;
}
__device__ __forceinline__ void cp16(unsigned dst, const void* src) {
    asm volatile("cp.async.cg.shared.global [%0], [%1], 16;"
                 :: "r"(dst), "l"(src));
}
#define CP_COMMIT() asm volatile("cp.async.commit_group;" ::: "memory")
#define CP_WAIT1()  asm volatile("cp.async.wait_group 1;" ::: "memory")
#define CP_WAIT0()  asm volatile("cp.async.wait_group 0;" ::: "memory")

// m16n8k8 tf32 MMA. g=lane>>2, t=lane&3.
__device__ __forceinline__ void mma8(float* d, unsigned a0, unsigned a1,
                                     unsigned a2, unsigned a3,
                                     unsigned b0, unsigned b1)
{
    asm("mma.sync.aligned.m16n8k8.row.col.f32.tf32.tf32.f32 "
        "{%0,%1,%2,%3},{%4,%5,%6,%7},{%8,%9},{%0,%1,%2,%3};"
        : "+f"(d[0]), "+f"(d[1]), "+f"(d[2]), "+f"(d[3])
        : "r"(a0), "r"(a1), "r"(a2), "r"(a3), "r"(b0), "r"(b1));
}
// m16n8k16 fp16 MMA, f32 accumulate.
__device__ __forceinline__ void mma16h(float* d, unsigned a0, unsigned a1,
                                       unsigned a2, unsigned a3,
                                       unsigned b0, unsigned b1)
{
    asm("mma.sync.aligned.m16n8k16.row.col.f32.f16.f16.f32 "
        "{%0,%1,%2,%3},{%4,%5,%6,%7},{%8,%9},{%0,%1,%2,%3};"
        : "+f"(d[0]), "+f"(d[1]), "+f"(d[2]), "+f"(d[3])
        : "r"(a0), "r"(a1), "r"(a2), "r"(a3), "r"(b0), "r"(b1));
}

// ===========================================================================
// Prep: round fp32 -> tf32 bits (rna), elementwise float4
// ===========================================================================
__global__ __launch_bounds__(256) void round_tf32_kernel(
    const float* __restrict__ src, float* __restrict__ dst, int n4)
{
    const int i = blockIdx.x * blockDim.x + threadIdx.x;
    if (i < n4) {
        float4 v = ((const float4*)src)[i];
        uint4 t = { f2tf32(v.x), f2tf32(v.y), f2tf32(v.z), f2tf32(v.w) };
        ((uint4*)dst)[i] = t;
    }
}

// ===========================================================================
// Transpose V: g_v [B,H,N,DK] fp32 -> g_vt [B,H,DK,N] fp16 (rn)
// Tile 64(n) x 64(d) per CTA. grid (NN/64, HH*BB), block 256.
// ===========================================================================
__global__ __launch_bounds__(256) void transpose_v_kernel()
{
    __shared__ float sm[64 * 65];
    const int tid = threadIdx.x;
    const int n0  = blockIdx.x * 64;
    const int bh  = blockIdx.y;

    const float* Vg = g_v + (size_t)bh * NN * DKK;
    __half* Vt = g_vt + (size_t)bh * DKK * NN;

    #pragma unroll
    for (int u = tid; u < 64 * 16; u += 256) {
        const int r  = u >> 4;
        const int c4 = (u & 15) << 2;
        float4 v = *(const float4*)(Vg + (size_t)(n0 + r) * DKK + c4);
        sm[r * 65 + c4 + 0] = v.x; sm[r * 65 + c4 + 1] = v.y;
        sm[r * 65 + c4 + 2] = v.z; sm[r * 65 + c4 + 3] = v.w;
    }
    __syncthreads();

    #pragma unroll
    for (int u = tid; u < 64 * 32; u += 256) {
        const int d = u >> 5;
        const int p = u & 31;
        const unsigned pk = pack_f16(sm[(2*p) * 65 + d], sm[(2*p+1) * 65 + d]);
        *(unsigned*)(Vt + (size_t)d * NN + n0 + 2*p) = pk;
    }
}

// ===========================================================================
// Tensor-core tf32 GEMM body (pre-rounded operands, plain fragment LDS).
// CTA 128x128, 4 warps, warp tile 64x64, K-chunk 32, cp.async double buffer.
// ===========================================================================
#define GSTR 36
#define GBUF (128*GSTR)
#define GEMM_SMEM (4*GBUF*4)     // 73728 bytes

__device__ __forceinline__ void gemm_cp_chunk(
    unsigned sA, unsigned sW,
    const float* __restrict__ A, const float* __restrict__ W,
    int tid, int row0, int col0, int chunk)
{
    #pragma unroll
    for (int k = 0; k < 8; k++) {
        const int u = tid + k * 128;
        const int r = u >> 3;
        const int c = u & 7;
        const unsigned soff = (unsigned)(r * GSTR + c * 4) * 4u;
        cp16(sA + soff, A + (size_t)(row0 + r) * MM + chunk * 32 + c * 4);
        cp16(sW + soff, W + (size_t)(col0 + r) * MM + chunk * 32 + c * 4);
    }
}

template<int HEADED>
__device__ __forceinline__ void gemm_body(
    const float* __restrict__ A, const float* __restrict__ W,
    const float* __restrict__ bias, float* __restrict__ C)
{
    extern __shared__ float gs[];
    const unsigned sbase = smem_u32(gs);

    const int tid  = threadIdx.x;
    const int w    = tid >> 5;
    const int lane = tid & 31;
    const int g    = lane >> 2;
    const int t    = lane & 3;
    const int row0 = blockIdx.y * 128;
    const int col0 = blockIdx.x * 128;
    const int wm   = (w >> 1) * 64;
    const int wn   = (w & 1) * 64;

    float c[4][8][4] = {};

    gemm_cp_chunk(sbase, sbase + 2*GBUF*4u, A, W, tid, row0, col0, 0);
    CP_COMMIT();

    for (int i = 0; i < 32; i++) {
        const int cur = i & 1;
        if (i + 1 < 32) {
            const int nxt = (i + 1) & 1;
            gemm_cp_chunk(sbase + nxt*GBUF*4u, sbase + (2+nxt)*GBUF*4u,
                          A, W, tid, row0, col0, i + 1);
            CP_COMMIT();
            CP_WAIT1();
        } else {
            CP_WAIT0();
        }
        __syncthreads();

        const float* Ab = gs + cur * GBUF;
        const float* Wb = gs + 2*GBUF + cur * GBUF;

        #pragma unroll
        for (int ks = 0; ks < 4; ks++) {
            const int kb = ks * 8;
            unsigned a[4][4];
            #pragma unroll
            for (int mt = 0; mt < 4; mt++) {
                const float* ar = Ab + (wm + mt * 16 + g) * GSTR + kb;
                a[mt][0] = __float_as_uint(ar[t]);
                a[mt][1] = __float_as_uint(ar[8 * GSTR + t]);
                a[mt][2] = __float_as_uint(ar[t + 4]);
                a[mt][3] = __float_as_uint(ar[8 * GSTR + t + 4]);
            }
            #pragma unroll
            for (int nt = 0; nt < 8; nt++) {
                const float* br = Wb + (wn + nt * 8 + g) * GSTR + kb;
                const unsigned b0 = __float_as_uint(br[t]);
                const unsigned b1 = __float_as_uint(br[t + 4]);
                #pragma unroll
                for (int mt = 0; mt < 4; mt++)
                    mma8(c[mt][nt], a[mt][0], a[mt][1], a[mt][2], a[mt][3], b0, b1);
            }
        }
        __syncthreads();
    }

    // Epilogue
    #pragma unroll
    for (int mt = 0; mt < 4; mt++) {
        const int r0 = row0 + wm + mt * 16 + g;
        const int r1 = r0 + 8;
        #pragma unroll
        for (int nt = 0; nt < 8; nt++) {
            const int col = col0 + wn + nt * 8 + 2 * t;
            const float bx = bias[col], by = bias[col + 1];
            float2 v0 = { c[mt][nt][0] + bx, c[mt][nt][1] + by };
            float2 v1 = { c[mt][nt][2] + bx, c[mt][nt][3] + by };
            if (HEADED) {
                v0.x = __uint_as_float(f2tf32(v0.x));
                v0.y = __uint_as_float(f2tf32(v0.y));
                v1.x = __uint_as_float(f2tf32(v1.x));
                v1.y = __uint_as_float(f2tf32(v1.y));
                const int h = col >> 6;
                const int d = col & 63;
                const int b0r = r0 >> 11, n0r = r0 & (NN - 1);
                const int b1r = r1 >> 11, n1r = r1 & (NN - 1);
                *(float2*)(C + (((size_t)(b0r*HH + h))*NN + n0r)*DKK + d) = v0;
                *(float2*)(C + (((size_t)(b1r*HH + h))*NN + n1r)*DKK + d) = v1;
            } else {
                *(float2*)(C + (size_t)r0 * MM + col) = v0;
                *(float2*)(C + (size_t)r1 * MM + col) = v1;
            }
        }
    }
}

__global__ __launch_bounds__(128, 2) void qkv_mma_kernel(
    const float* __restrict__ A, const float* __restrict__ Wt,
    const float* __restrict__ bq, const float* __restrict__ bk,
    const float* __restrict__ bv,
    float* __restrict__ dq, float* __restrict__ dk, float* __restrict__ dv)
{
    const int z = blockIdx.z;
    const float* W    = Wt + (size_t)z * MM * MM;
    const float* bias = (z == 0) ? bq : (z == 1) ? bk : bv;
    float*       C    = (z == 0) ? dq : (z == 1) ? dk : dv;
    gemm_body<1>(A, W, bias, C);
}

__global__ __launch_bounds__(128, 2) void out_mma_kernel(
    const float* __restrict__ A, const float* __restrict__ W,
    const float* __restrict__ bias, float* __restrict__ C)
{
    gemm_body<0>(A, W, bias, C);
}

// ===========================================================================
// Flash attention. QK: tf32 m16n8k8. PV: fp16 m16n8k16 (C-frag of S == A-frag
// of P: no transpose, no shuffle). V pre-transposed fp16 in smem; rowsum of P
// via ones row (d=64) in V padding -> tensor pipe computes l.
// CTA = 128 q-rows, 4 warps, warp = 32 rows. kv tile 64, double-buffered.
// ===========================================================================
#define FSTR 72
#define FQ_OFF  0
#define FK_OFF  9216
#define FKV     4608                          // K buffer floats
#define FV_OFF  18432                         // float index of fp16 V region
#define VBUF    5184                          // fp16 elems per V buffer (72x72)
#define FLASH_SMEM (18432*4 + 2*VBUF*2)       // 94464 bytes

__device__ __forceinline__ void flash_cp_k(
    unsigned sK, const float* __restrict__ Kg, int tid, int k0)
{
    #pragma unroll
    for (int j = 0; j < 8; j++) {
        const int u = tid + j * 128;
        const int r = u >> 4;
        const int cc = (u & 15) << 2;
        cp16(sK + (unsigned)(r * FSTR + cc) * 4u, Kg + (size_t)(k0 + r) * DKK + cc);
    }
}
__device__ __forceinline__ void flash_cp_v(
    unsigned sV, const __half* __restrict__ Vtg, int tid, int k0)
{
    #pragma unroll
    for (int j = 0; j < 4; j++) {
        const int u = tid + j * 128;
        const int d = u >> 3;               // 0..63
        const int c8 = (u & 7) << 3;        // fp16 col offset 0..56
        cp16(sV + (unsigned)(d * 72 + c8) * 2u, Vtg + (size_t)d * NN + k0 + c8);
    }
}

__global__ __launch_bounds__(128, 2) void flash_mma_kernel(
    const float* __restrict__ mask, float* __restrict__ out)
{
    extern __shared__ float fs[];
    const unsigned sbase = smem_u32(fs);
    __half* vb = (__half*)(fs + FV_OFF);

    const int tid  = threadIdx.x;
    const int w    = tid >> 5;
    const int lane = tid & 31;
    const int g    = lane >> 2;
    const int t    = lane & 3;
    const int q0   = blockIdx.x * 128;
    const int h    = blockIdx.y;
    const int b    = blockIdx.z;

    const float* Qg = g_q + (((size_t)(b*HH + h)) * NN) * DKK;
    const float* Kg = g_k + (((size_t)(b*HH + h)) * NN) * DKK;
    const __half* Vtg = g_vt + (size_t)(b*HH + h) * DKK * NN;
    const float* Mg = mask + (size_t)b * NN * NN;

    // Stage Q, scaled by 0.125*log2(e), rna tf32 — once.
    const float qscale = 0.125f * 1.4426950408889634f;
    for (int u = tid; u < 128 * 16; u += 128) {
        const int r  = u >> 4;
        const int cc = (u & 15) << 2;
        float4 v = *(const float4*)(Qg + (size_t)(q0 + r) * DKK + cc);
        uint4 tv = { f2tf32(v.x * qscale), f2tf32(v.y * qscale),
                     f2tf32(v.z * qscale), f2tf32(v.w * qscale) };
        *(uint4*)(fs + FQ_OFF + r * FSTR + cc) = tv;
    }

    // Init V pad rows 64..71 (both buffers): row 64 = 1.0, rows 65..71 = 0.
    {
        const __half one  = __float2half(1.0f);
        const __half zero = __float2half(0.0f);
        for (int u = tid; u < 8 * 72; u += 128) {
            const int r = 64 + u / 72;
            const int c = u % 72;
            const __half val = (r == 64) ? one : zero;
            vb[r * 72 + c]        = val;
            vb[VBUF + r * 72 + c] = val;
        }
    }
    __syncthreads();

    flash_cp_k(sbase + FK_OFF*4u, Kg, tid, 0);
    flash_cp_v(sbase + FV_OFF*4u, Vtg, tid, 0);
    CP_COMMIT();

    float o[2][8][4] = {};
    float ol[2][4] = {};

    const int qw = q0 + w * 32;

    for (int it = 0; it < 32; it++) {
        const int k0  = it * 64;
        const int cur = it & 1;
        if (it + 1 < 32) {
            const int nxt = (it + 1) & 1;
            flash_cp_k(sbase + (FK_OFF + nxt*FKV)*4u, Kg, tid, k0 + 64);
            flash_cp_v(sbase + FV_OFF*4u + (unsigned)nxt*VBUF*2u, Vtg, tid, k0 + 64);
            CP_COMMIT();
            CP_WAIT1();
        } else {
            CP_WAIT0();
        }
        __syncthreads();

        const float* Ks = fs + FK_OFF + cur * FKV;
        const __half* Vs = vb + cur * VBUF;

        // ---- S~ = (Q*log2e/8) * K^T  (tf32) ----
        float s[2][8][4] = {};
        #pragma unroll
        for (int ks = 0; ks < 8; ks++) {
            const int kb = ks * 8;
            unsigned aq[2][4];
            #pragma unroll
            for (int mt = 0; mt < 2; mt++) {
                const float* ar = fs + FQ_OFF + (w*32 + mt*16 + g) * FSTR + kb;
                aq[mt][0] = __float_as_uint(ar[t]);
                aq[mt][1] = __float_as_uint(ar[8 * FSTR + t]);
                aq[mt][2] = __float_as_uint(ar[t + 4]);
                aq[mt][3] = __float_as_uint(ar[8 * FSTR + t + 4]);
            }
            #pragma unroll
            for (int nt = 0; nt < 8; nt++) {
                const float* br = Ks + (nt * 8 + g) * FSTR + kb;
                const unsigned b0 = __float_as_uint(br[t]);
                const unsigned b1 = __float_as_uint(br[t + 4]);
                mma8(s[0][nt], aq[0][0], aq[0][1], aq[0][2], aq[0][3], b0, b1);
                mma8(s[1][nt], aq[1][0], aq[1][1], aq[1][2], aq[1][3], b0, b1);
            }
        }

        // ---- p = exp2(s~ * mask) ----
        #pragma unroll
        for (int mt = 0; mt < 2; mt++) {
            const float* Mr0 = Mg + (size_t)(qw + mt*16 + g) * NN + k0;
            const float* Mr1 = Mr0 + 8 * NN;
            #pragma unroll
            for (int nt = 0; nt < 8; nt++) {
                float2 ma = *(const float2*)(Mr0 + nt * 8 + 2 * t);
                float2 mb = *(const float2*)(Mr1 + nt * 8 + 2 * t);
                s[mt][nt][0] = ex2f(s[mt][nt][0] * ma.x);
                s[mt][nt][1] = ex2f(s[mt][nt][1] * ma.y);
                s[mt][nt][2] = ex2f(s[mt][nt][2] * mb.x);
                s[mt][nt][3] = ex2f(s[mt][nt][3] * mb.y);
            }
        }

        // ---- O += P * V  (fp16 m16n8k16; A-frags straight from S C-frags) ----
        #pragma unroll
        for (int kk = 0; kk < 4; kk++) {
            unsigned a[2][4];
            #pragma unroll
            for (int mt = 0; mt < 2; mt++) {
                a[mt][0] = pack_f16(s[mt][2*kk][0],   s[mt][2*kk][1]);
                a[mt][1] = pack_f16(s[mt][2*kk][2],   s[mt][2*kk][3]);
                a[mt][2] = pack_f16(s[mt][2*kk+1][0], s[mt][2*kk+1][1]);
                a[mt][3] = pack_f16(s[mt][2*kk+1][2], s[mt][2*kk+1][3]);
            }
            const int kb = kk * 16;
            #pragma unroll
            for (int nt = 0; nt < 8; nt++) {
                const __half* br = Vs + (nt * 8 + g) * 72 + kb + 2 * t;
                const unsigned b0 = *(const unsigned*)br;
                const unsigned b1 = *(const unsigned*)(br + 8);
                mma16h(o[0][nt], a[0][0], a[0][1], a[0][2], a[0][3], b0, b1);
                mma16h(o[1][nt], a[1][0], a[1][1], a[1][2], a[1][3], b0, b1);
            }
            // ones tile (rows 64..71 of Vs): accumulates row sums into col 0
            {
                const __half* br = Vs + (64 + g) * 72 + kb + 2 * t;
                const unsigned b0 = *(const unsigned*)br;
                const unsigned b1 = *(const unsigned*)(br + 8);
                mma16h(ol[0], a[0][0], a[0][1], a[0][2], a[0][3], b0, b1);
                mma16h(ol[1], a[1][0], a[1][1], a[1][2], a[1][3], b0, b1);
            }
        }
        __syncthreads();
    }

    // ---- l broadcast (rowsum at quad lane t=0: c0=row g, c2=row g+8) ----
    #pragma unroll
    for (int mt = 0; mt < 2; mt++) {
        const float l0 = __shfl_sync(0xffffffffu, ol[mt][0], lane & 28);
        const float l1 = __shfl_sync(0xffffffffu, ol[mt][2], lane & 28);
        const float il0 = 1.0f / l0;
        const float il1 = 1.0f / l1;
        float* Or0 = out + ((size_t)b * NN + qw + mt*16 + g) * MM + h * DKK;
        float* Or1 = Or0 + 8 * MM;
        #pragma unroll
        for (int nt = 0; nt < 8; nt++) {
            float2 v0 = { __uint_as_float(f2tf32(o[mt][nt][0] * il0)),
                          __uint_as_float(f2tf32(o[mt][nt][1] * il0)) };
            float2 v1 = { __uint_as_float(f2tf32(o[mt][nt][2] * il1)),
                          __uint_as_float(f2tf32(o[mt][nt][3] * il1)) };
            *(float2*)(Or0 + nt * 8 + 2 * t) = v0;
            *(float2*)(Or1 + nt * 8 + 2 * t) = v1;
        }
    }
}

// ===========================================================================
extern "C" void kernel_launch(void* const* d_in, const int* in_sizes, int n_in,
                              void* d_out, int out_size)
{
    const float* x    = (const float*)d_in[0];
    const float* mask = (const float*)d_in[1];
    const float* Wq   = (const float*)d_in[2];
    const float* bq   = (const float*)d_in[3];
    const float* Wk   = (const float*)d_in[4];
    const float* bk   = (const float*)d_in[5];
    const float* Wv   = (const float*)d_in[6];
    const float* bv   = (const float*)d_in[7];
    const float* Wo   = (const float*)d_in[8];
    const float* bo   = (const float*)d_in[9];
    float* out = (float*)d_out;

    void *pq, *pk, *pv, *pa, *pxt, *pwt;
    cudaGetSymbolAddress(&pq,  g_q);
    cudaGetSymbolAddress(&pk,  g_k);
    cudaGetSymbolAddress(&pv,  g_v);
    cudaGetSymbolAddress(&pa,  g_att);
    cudaGetSymbolAddress(&pxt, g_xt);
    cudaGetSymbolAddress(&pwt, g_wt);

    float* xt = (float*)pxt;
    float* wt = (float*)pwt;

    cudaFuncSetAttribute(qkv_mma_kernel,
                         cudaFuncAttributeMaxDynamicSharedMemorySize, GEMM_SMEM);
    cudaFuncSetAttribute(out_mma_kernel,
                         cudaFuncAttributeMaxDynamicSharedMemorySize, GEMM_SMEM);
    cudaFuncSetAttribute(flash_mma_kernel,
                         cudaFuncAttributeMaxDynamicSharedMemorySize, FLASH_SMEM);

    // Pre-round operands to tf32 (rna) once.
    round_tf32_kernel<<<(ROWS*MM/4 + 255)/256, 256>>>(x,  xt, ROWS*MM/4);
    round_tf32_kernel<<<(MM*MM/4 + 255)/256, 256>>>(Wq, wt + 0*MM*MM, MM*MM/4);
    round_tf32_kernel<<<(MM*MM/4 + 255)/256, 256>>>(Wk, wt + 1*MM*MM, MM*MM/4);
    round_tf32_kernel<<<(MM*MM/4 + 255)/256, 256>>>(Wv, wt + 2*MM*MM, MM*MM/4);
    round_tf32_kernel<<<(MM*MM/4 + 255)/256, 256>>>(Wo, wt + 3*MM*MM, MM*MM/4);

    // Fused Q/K/V projections
    dim3 qkv_grid(MM/128, ROWS/128, 3);   // (8, 32, 3)
    qkv_mma_kernel<<<qkv_grid, 128, GEMM_SMEM>>>(
        xt, wt, bq, bk, bv, (float*)pq, (float*)pk, (float*)pv);

    // V -> fp16 transposed
    dim3 tv_grid(NN/64, HH*BB);           // (32, 32)
    transpose_v_kernel<<<tv_grid, 256>>>();

    // Fused attention
    dim3 attn_grid(NN/128, HH, BB);       // (16, 16, 2)
    flash_mma_kernel<<<attn_grid, 128, FLASH_SMEM>>>(mask, (float*)pa);

    // Output projection
    dim3 out_grid(MM/128, ROWS/128);      // (8, 32)
    out_mma_kernel<<<out_grid, 128, GEMM_SMEM>>>((const float*)pa, wt + 3*MM*MM, bo, out);
}

// round 9
// speedup vs baseline: 7.1597x; 1.5620x over previous
#include <cuda_runtime.h>
#include <cuda_fp16.h>

// Problem constants
#define BB   2
#define NN   2048
#define MM   1024
#define HH   16
#define DKK  64
#define ROWS (BB*NN)   // 4096

// Scratch (allocation-free rule: __device__ globals) — all fp16 now
__device__ __half g_q [BB*HH*NN*DKK];     // Q, pre-scaled by 0.125*log2(e)
__device__ __half g_k [BB*HH*NN*DKK];
__device__ __half g_v [BB*HH*NN*DKK];
__device__ __half g_vt[BB*HH*DKK*NN];     // V transposed
__device__ __half g_ath[BB*NN*MM];        // attention output (concat layout)
__device__ __half g_xh[ROWS*MM];          // fp16 x
__device__ __half g_wh[4*MM*MM];          // fp16 Wq,Wk,Wv,Wo

// ===========================================================================
// Helpers
// ===========================================================================
__device__ __forceinline__ unsigned smem_u32(const void* p) {
    unsigned a;
    asm("{ .reg .u64 t; cvta.to.shared.u64 t, %1; cvt.u32.u64 %0, t; }"
        : "=r"(a) : "l"(p));
    return a;
}
__device__ __forceinline__ float ex2f(float x) {
    float r;
    asm("ex2.approx.f32 %0, %1;" : "=f"(r) : "f"(x));
    return r;
}
__device__ __forceinline__ unsigned pack_f16(float lo, float hi) {
    unsigned r;
    asm("cvt.rn.f16x2.f32 %0, %1, %2;" : "=r"(r) : "f"(hi), "f"(lo));
    return r;
}
__device__ __forceinline__ void cp16(unsigned dst, const void* src) {
    asm volatile("cp.async.cg.shared.global [%0], [%1], 16;"
                 :: "r"(dst), "l"(src));
}
#define CP_COMMIT() asm volatile("cp.async.commit_group;" ::: "memory")
#define CP_WAIT1()  asm volatile("cp.async.wait_group 1;" ::: "memory")
#define CP_WAIT0()  asm volatile("cp.async.wait_group 0;" ::: "memory")

// m16n8k16 fp16 MMA, f32 accumulate. g=lane>>2, t=lane&3.
// A: a0=(g, k=2t,2t+1) a1=(g+8, 2t) a2=(g, 2t+8) a3=(g+8, 2t+8)
// B: b0=(k=2t,2t+1, n=g) b1=(k=2t+8, n=g)
// C: c0=(g,2t) c1=(g,2t+1) c2=(g+8,2t) c3=(g+8,2t+1)
__device__ __forceinline__ void mma16h(float* d, unsigned a0, unsigned a1,
                                       unsigned a2, unsigned a3,
                                       unsigned b0, unsigned b1)
{
    asm("mma.sync.aligned.m16n8k16.row.col.f32.f16.f16.f32 "
        "{%0,%1,%2,%3},{%4,%5,%6,%7},{%8,%9},{%0,%1,%2,%3};"
        : "+f"(d[0]), "+f"(d[1]), "+f"(d[2]), "+f"(d[3])
        : "r"(a0), "r"(a1), "r"(a2), "r"(a3), "r"(b0), "r"(b1));
}

// ===========================================================================
// Prep: fp32 -> fp16 (rn), elementwise
// ===========================================================================
__global__ __launch_bounds__(256) void cvt_f16_kernel(
    const float* __restrict__ src, __half* __restrict__ dst, int n4)
{
    const int i = blockIdx.x * blockDim.x + threadIdx.x;
    if (i < n4) {
        float4 v = ((const float4*)src)[i];
        uint2 p = { pack_f16(v.x, v.y), pack_f16(v.z, v.w) };
        *(uint2*)(dst + (size_t)i * 4) = p;
    }
}
// Convert the 4 weight matrices (grid.y selects)
__global__ __launch_bounds__(256) void cvt_w_kernel(
    const float* __restrict__ W0, const float* __restrict__ W1,
    const float* __restrict__ W2, const float* __restrict__ W3,
    __half* __restrict__ dst)
{
    const int z = blockIdx.y;
    const float* src = (z == 0) ? W0 : (z == 1) ? W1 : (z == 2) ? W2 : W3;
    const int i = blockIdx.x * blockDim.x + threadIdx.x;
    if (i < MM*MM/4) {
        float4 v = ((const float4*)src)[i];
        uint2 p = { pack_f16(v.x, v.y), pack_f16(v.z, v.w) };
        *(uint2*)(dst + (size_t)z * MM * MM + (size_t)i * 4) = p;
    }
}

// ===========================================================================
// Transpose V: g_v [B,H,N,DK] -> g_vt [B,H,DK,N], fp16
// Tile 64(n) x 64(d). grid (NN/64, HH*BB), block 256.
// ===========================================================================
__global__ __launch_bounds__(256) void transpose_v_kernel()
{
    __shared__ __half sm[64 * 72];
    const int tid = threadIdx.x;
    const int n0  = blockIdx.x * 64;
    const int bh  = blockIdx.y;

    const __half* Vg = g_v + (size_t)bh * NN * DKK;
    __half* Vt = g_vt + (size_t)bh * DKK * NN;

    #pragma unroll
    for (int u = tid; u < 64 * 32; u += 256) {
        const int r  = u >> 5;
        const int c2 = (u & 31) << 1;
        *(unsigned*)(sm + r * 72 + c2) =
            *(const unsigned*)(Vg + (size_t)(n0 + r) * DKK + c2);
    }
    __syncthreads();

    #pragma unroll
    for (int u = tid; u < 64 * 32; u += 256) {
        const int d = u >> 5;
        const int p = u & 31;
        const unsigned pk = pack_f16(__half2float(sm[(2*p) * 72 + d]),
                                     __half2float(sm[(2*p+1) * 72 + d]));
        *(unsigned*)(Vt + (size_t)d * NN + n0 + 2*p) = pk;
    }
}

// ===========================================================================
// fp16 GEMM body: C[r,c] = (sum_k A[r,k]*W[c,k] + bias[c]) * oscale
// CTA 128x128, 4 warps, warp tile 64x64, K-chunk 64, cp.async double buffer.
// Stride 72 halves -> all fragment LDS conflict-free.
// HEADED=1: scatter fp16 to [B,H,N,DK]. HEADED=0: fp32 flat [ROWS,MM].
// ===========================================================================
#define GSTRH 72
#define GBUFH (128*GSTRH)            // 9216 halves per buffer
#define GEMM_SMEM (4*GBUFH*2)        // 73728 bytes

__device__ __forceinline__ void gemm_cp_chunk(
    unsigned sA, unsigned sW,
    const __half* __restrict__ A, const __half* __restrict__ W,
    int tid, int row0, int col0, int chunk)
{
    #pragma unroll
    for (int k = 0; k < 8; k++) {
        const int u = tid + k * 128;
        const int r = u >> 3;
        const int c = u & 7;                 // 16B unit within 64-half row
        const unsigned soff = (unsigned)(r * GSTRH + c * 8) * 2u;
        cp16(sA + soff, A + (size_t)(row0 + r) * MM + chunk * 64 + c * 8);
        cp16(sW + soff, W + (size_t)(col0 + r) * MM + chunk * 64 + c * 8);
    }
}

template<int HEADED>
__device__ __forceinline__ void gemm_body(
    const __half* __restrict__ A, const __half* __restrict__ W,
    const float* __restrict__ bias, void* __restrict__ Cv, float oscale)
{
    extern __shared__ __half hs[];
    const unsigned sbase = smem_u32(hs);

    const int tid  = threadIdx.x;
    const int w    = tid >> 5;
    const int lane = tid & 31;
    const int g    = lane >> 2;
    const int t    = lane & 3;
    const int row0 = blockIdx.y * 128;
    const int col0 = blockIdx.x * 128;
    const int wm   = (w >> 1) * 64;
    const int wn   = (w & 1) * 64;

    float c[4][8][4] = {};

    gemm_cp_chunk(sbase, sbase + 2*GBUFH*2u, A, W, tid, row0, col0, 0);
    CP_COMMIT();

    for (int i = 0; i < 16; i++) {
        const int cur = i & 1;
        if (i + 1 < 16) {
            const int nxt = (i + 1) & 1;
            gemm_cp_chunk(sbase + nxt*GBUFH*2u, sbase + (2+nxt)*GBUFH*2u,
                          A, W, tid, row0, col0, i + 1);
            CP_COMMIT();
            CP_WAIT1();
        } else {
            CP_WAIT0();
        }
        __syncthreads();

        const __half* Ab = hs + cur * GBUFH;
        const __half* Wb = hs + 2*GBUFH + cur * GBUFH;

        #pragma unroll
        for (int ks = 0; ks < 4; ks++) {
            const int kb = ks * 16;
            unsigned a[4][4];
            #pragma unroll
            for (int mt = 0; mt < 4; mt++) {
                const __half* ar = Ab + (wm + mt * 16 + g) * GSTRH + kb + 2 * t;
                a[mt][0] = *(const unsigned*)ar;
                a[mt][1] = *(const unsigned*)(ar + 8 * GSTRH);
                a[mt][2] = *(const unsigned*)(ar + 8);
                a[mt][3] = *(const unsigned*)(ar + 8 * GSTRH + 8);
            }
            #pragma unroll
            for (int nt = 0; nt < 8; nt++) {
                const __half* br = Wb + (wn + nt * 8 + g) * GSTRH + kb + 2 * t;
                const unsigned b0 = *(const unsigned*)br;
                const unsigned b1 = *(const unsigned*)(br + 8);
                #pragma unroll
                for (int mt = 0; mt < 4; mt++)
                    mma16h(c[mt][nt], a[mt][0], a[mt][1], a[mt][2], a[mt][3], b0, b1);
            }
        }
        __syncthreads();
    }

    // Epilogue
    #pragma unroll
    for (int mt = 0; mt < 4; mt++) {
        const int r0 = row0 + wm + mt * 16 + g;
        const int r1 = r0 + 8;
        #pragma unroll
        for (int nt = 0; nt < 8; nt++) {
            const int col = col0 + wn + nt * 8 + 2 * t;
            const float bx = bias[col], by = bias[col + 1];
            if (HEADED) {
                __half* C = (__half*)Cv;
                const unsigned p0 = pack_f16((c[mt][nt][0] + bx) * oscale,
                                             (c[mt][nt][1] + by) * oscale);
                const unsigned p1 = pack_f16((c[mt][nt][2] + bx) * oscale,
                                             (c[mt][nt][3] + by) * oscale);
                const int h = col >> 6;
                const int d = col & 63;
                const int b0r = r0 >> 11, n0r = r0 & (NN - 1);
                const int b1r = r1 >> 11, n1r = r1 & (NN - 1);
                *(unsigned*)(C + (((size_t)(b0r*HH + h))*NN + n0r)*DKK + d) = p0;
                *(unsigned*)(C + (((size_t)(b1r*HH + h))*NN + n1r)*DKK + d) = p1;
            } else {
                float* C = (float*)Cv;
                float2 v0 = { c[mt][nt][0] + bx, c[mt][nt][1] + by };
                float2 v1 = { c[mt][nt][2] + bx, c[mt][nt][3] + by };
                *(float2*)(C + (size_t)r0 * MM + col) = v0;
                *(float2*)(C + (size_t)r1 * MM + col) = v1;
            }
        }
    }
}

__global__ __launch_bounds__(128, 2) void qkv_mma_kernel(
    const __half* __restrict__ A, const __half* __restrict__ Wt,
    const float* __restrict__ bq, const float* __restrict__ bk,
    const float* __restrict__ bv, float qscale)
{
    const int z = blockIdx.z;
    const __half* W   = Wt + (size_t)z * MM * MM;
    const float* bias = (z == 0) ? bq : (z == 1) ? bk : bv;
    __half*      C    = (z == 0) ? g_q : (z == 1) ? g_k : g_v;
    gemm_body<1>(A, W, bias, C, (z == 0) ? qscale : 1.0f);
}

__global__ __launch_bounds__(128, 2) void out_mma_kernel(
    const __half* __restrict__ A, const __half* __restrict__ W,
    const float* __restrict__ bias, float* __restrict__ C)
{
    gemm_body<0>(A, W, bias, C, 1.0f);
}

// ===========================================================================
// Flash attention, all-fp16 MMA (f32 accum), no online softmax.
// QK: m16n8k16 fp16 (Q pre-scaled in projection). PV: m16n8k16 fp16
// (S C-frag == P A-frag). V pre-transposed; rowsum via ones row in V pad.
// CTA = 128 q-rows, 4 warps, warp = 32 rows. kv tile 64, double-buffered.
// Smem halves: Q[0,9216) K0/K1[9216,18432) V0/V1[18432,28800) = 57600 B.
// ===========================================================================
#define HQ_OFF  0
#define HK_OFF  9216
#define HKBUF   4608
#define HV_OFF  18432
#define HVBUF   5184
#define FLASH_SMEM (28800 * 2)   // 57600 bytes

__device__ __forceinline__ void flash_cp_q(
    unsigned sQ, const __half* __restrict__ Qg, int tid, int q0)
{
    #pragma unroll
    for (int j = 0; j < 8; j++) {
        const int u = tid + j * 128;
        const int r = u >> 3;
        const int c = u & 7;
        cp16(sQ + (unsigned)(r * GSTRH + c * 8) * 2u,
             Qg + (size_t)(q0 + r) * DKK + c * 8);
    }
}
__device__ __forceinline__ void flash_cp_k(
    unsigned sK, const __half* __restrict__ Kg, int tid, int k0)
{
    #pragma unroll
    for (int j = 0; j < 4; j++) {
        const int u = tid + j * 128;
        const int r = u >> 3;
        const int c = u & 7;
        cp16(sK + (unsigned)(r * GSTRH + c * 8) * 2u,
             Kg + (size_t)(k0 + r) * DKK + c * 8);
    }
}
__device__ __forceinline__ void flash_cp_v(
    unsigned sV, const __half* __restrict__ Vtg, int tid, int k0)
{
    #pragma unroll
    for (int j = 0; j < 4; j++) {
        const int u = tid + j * 128;
        const int d = u >> 3;
        const int c = u & 7;
        cp16(sV + (unsigned)(d * GSTRH + c * 8) * 2u,
             Vtg + (size_t)d * NN + k0 + c * 8);
    }
}

__global__ __launch_bounds__(128, 2) void flash_mma_kernel(
    const float* __restrict__ mask, __half* __restrict__ out)
{
    extern __shared__ __half hs[];
    const unsigned sbase = smem_u32(hs);

    const int tid  = threadIdx.x;
    const int w    = tid >> 5;
    const int lane = tid & 31;
    const int g    = lane >> 2;
    const int t    = lane & 3;
    const int q0   = blockIdx.x * 128;
    const int h    = blockIdx.y;
    const int b    = blockIdx.z;

    const __half* Qg  = g_q + (((size_t)(b*HH + h)) * NN) * DKK;
    const __half* Kg  = g_k + (((size_t)(b*HH + h)) * NN) * DKK;
    const __half* Vtg = g_vt + (size_t)(b*HH + h) * DKK * NN;
    const float*  Mg  = mask + (size_t)b * NN * NN;

    // V pad rows 64..71 (both buffers): row 64 = 1.0 (ones), rest 0.
    {
        const __half one  = __float2half(1.0f);
        const __half zero = __float2half(0.0f);
        for (int u = tid; u < 8 * GSTRH; u += 128) {
            const int r = 64 + u / GSTRH;
            const int c = u % GSTRH;
            const __half val = (r == 64) ? one : zero;
            hs[HV_OFF + r * GSTRH + c]         = val;
            hs[HV_OFF + HVBUF + r * GSTRH + c] = val;
        }
    }

    flash_cp_q(sbase + HQ_OFF*2u, Qg, tid, q0);
    flash_cp_k(sbase + HK_OFF*2u, Kg, tid, 0);
    flash_cp_v(sbase + HV_OFF*2u, Vtg, tid, 0);
    CP_COMMIT();

    float o[2][8][4] = {};
    float ol[2][4] = {};

    const int qw = q0 + w * 32;

    for (int it = 0; it < 32; it++) {
        const int k0  = it * 64;
        const int cur = it & 1;
        if (it + 1 < 32) {
            const int nxt = (it + 1) & 1;
            flash_cp_k(sbase + (HK_OFF + nxt*HKBUF)*2u, Kg, tid, k0 + 64);
            flash_cp_v(sbase + (HV_OFF + nxt*HVBUF)*2u, Vtg, tid, k0 + 64);
            CP_COMMIT();
            CP_WAIT1();
        } else {
            CP_WAIT0();
        }
        __syncthreads();

        const __half* Ks = hs + HK_OFF + cur * HKBUF;
        const __half* Vs = hs + HV_OFF + cur * HVBUF;

        // ---- S~ = Qs * K^T  (fp16, k-steps of 16) ----
        float s[2][8][4] = {};
        #pragma unroll
        for (int ks = 0; ks < 4; ks++) {
            const int kb = ks * 16;
            unsigned aq[2][4];
            #pragma unroll
            for (int mt = 0; mt < 2; mt++) {
                const __half* ar = hs + HQ_OFF + (w*32 + mt*16 + g) * GSTRH + kb + 2*t;
                aq[mt][0] = *(const unsigned*)ar;
                aq[mt][1] = *(const unsigned*)(ar + 8 * GSTRH);
                aq[mt][2] = *(const unsigned*)(ar + 8);
                aq[mt][3] = *(const unsigned*)(ar + 8 * GSTRH + 8);
            }
            #pragma unroll
            for (int nt = 0; nt < 8; nt++) {
                const __half* br = Ks + (nt * 8 + g) * GSTRH + kb + 2 * t;
                const unsigned b0 = *(const unsigned*)br;
                const unsigned b1 = *(const unsigned*)(br + 8);
                mma16h(s[0][nt], aq[0][0], aq[0][1], aq[0][2], aq[0][3], b0, b1);
                mma16h(s[1][nt], aq[1][0], aq[1][1], aq[1][2], aq[1][3], b0, b1);
            }
        }

        // ---- p = exp2(s~ * mask) ----
        #pragma unroll
        for (int mt = 0; mt < 2; mt++) {
            const float* Mr0 = Mg + (size_t)(qw + mt*16 + g) * NN + k0;
            const float* Mr1 = Mr0 + 8 * NN;
            #pragma unroll
            for (int nt = 0; nt < 8; nt++) {
                float2 ma = *(const float2*)(Mr0 + nt * 8 + 2 * t);
                float2 mb = *(const float2*)(Mr1 + nt * 8 + 2 * t);
                s[mt][nt][0] = ex2f(s[mt][nt][0] * ma.x);
                s[mt][nt][1] = ex2f(s[mt][nt][1] * ma.y);
                s[mt][nt][2] = ex2f(s[mt][nt][2] * mb.x);
                s[mt][nt][3] = ex2f(s[mt][nt][3] * mb.y);
            }
        }

        // ---- O += P * V  (A-frags straight from S C-frags) ----
        #pragma unroll
        for (int kk = 0; kk < 4; kk++) {
            unsigned a[2][4];
            #pragma unroll
            for (int mt = 0; mt < 2; mt++) {
                a[mt][0] = pack_f16(s[mt][2*kk][0],   s[mt][2*kk][1]);
                a[mt][1] = pack_f16(s[mt][2*kk][2],   s[mt][2*kk][3]);
                a[mt][2] = pack_f16(s[mt][2*kk+1][0], s[mt][2*kk+1][1]);
                a[mt][3] = pack_f16(s[mt][2*kk+1][2], s[mt][2*kk+1][3]);
            }
            const int kb = kk * 16;
            #pragma unroll
            for (int nt = 0; nt < 8; nt++) {
                const __half* br = Vs + (nt * 8 + g) * GSTRH + kb + 2 * t;
                const unsigned b0 = *(const unsigned*)br;
                const unsigned b1 = *(const unsigned*)(br + 8);
                mma16h(o[0][nt], a[0][0], a[0][1], a[0][2], a[0][3], b0, b1);
                mma16h(o[1][nt], a[1][0], a[1][1], a[1][2], a[1][3], b0, b1);
            }
            {
                const __half* br = Vs + (64 + g) * GSTRH + kb + 2 * t;
                const unsigned b0 = *(const unsigned*)br;
                const unsigned b1 = *(const unsigned*)(br + 8);
                mma16h(ol[0], a[0][0], a[0][1], a[0][2], a[0][3], b0, b1);
                mma16h(ol[1], a[1][0], a[1][1], a[1][2], a[1][3], b0, b1);
            }
        }
        __syncthreads();
    }

    // ---- l broadcast + normalize + write concat [B,N,M] fp16 ----
    #pragma unroll
    for (int mt = 0; mt < 2; mt++) {
        const float l0 = __shfl_sync(0xffffffffu, ol[mt][0], lane & 28);
        const float l1 = __shfl_sync(0xffffffffu, ol[mt][2], lane & 28);
        const float il0 = 1.0f / l0;
        const float il1 = 1.0f / l1;
        __half* Or0 = out + ((size_t)b * NN + qw + mt*16 + g) * MM + h * DKK;
        __half* Or1 = Or0 + 8 * MM;
        #pragma unroll
        for (int nt = 0; nt < 8; nt++) {
            const unsigned p0 = pack_f16(o[mt][nt][0] * il0, o[mt][nt][1] * il0);
            const unsigned p1 = pack_f16(o[mt][nt][2] * il1, o[mt][nt][3] * il1);
            *(unsigned*)(Or0 + nt * 8 + 2 * t) = p0;
            *(unsigned*)(Or1 + nt * 8 + 2 * t) = p1;
        }
    }
}

// ===========================================================================
extern "C" void kernel_launch(void* const* d_in, const int* in_sizes, int n_in,
                              void* d_out, int out_size)
{
    const float* x    = (const float*)d_in[0];
    const float* mask = (const float*)d_in[1];
    const float* Wq   = (const float*)d_in[2];
    const float* bq   = (const float*)d_in[3];
    const float* Wk   = (const float*)d_in[4];
    const float* bk   = (const float*)d_in[5];
    const float* Wv   = (const float*)d_in[6];
    const float* bv   = (const float*)d_in[7];
    const float* Wo   = (const float*)d_in[8];
    const float* bo   = (const float*)d_in[9];
    float* out = (float*)d_out;

    void *pxh, *pwh, *path;
    cudaGetSymbolAddress(&pxh,  g_xh);
    cudaGetSymbolAddress(&pwh,  g_wh);
    cudaGetSymbolAddress(&path, g_ath);
    __half* xh  = (__half*)pxh;
    __half* wh  = (__half*)pwh;
    __half* ath = (__half*)path;

    cudaFuncSetAttribute(qkv_mma_kernel,
                         cudaFuncAttributeMaxDynamicSharedMemorySize, GEMM_SMEM);
    cudaFuncSetAttribute(out_mma_kernel,
                         cudaFuncAttributeMaxDynamicSharedMemorySize, GEMM_SMEM);
    cudaFuncSetAttribute(flash_mma_kernel,
                         cudaFuncAttributeMaxDynamicSharedMemorySize, FLASH_SMEM);

    // Convert inputs to fp16 once.
    cvt_f16_kernel<<<(ROWS*MM/4 + 255)/256, 256>>>(x, xh, ROWS*MM/4);
    dim3 w_grid((MM*MM/4 + 255)/256, 4);
    cvt_w_kernel<<<w_grid, 256>>>(Wq, Wk, Wv, Wo, wh);

    // Fused Q/K/V projections (Q pre-scaled by 0.125*log2(e))
    const float qscale = 0.125f * 1.4426950408889634f;
    dim3 qkv_grid(MM/128, ROWS/128, 3);   // (8, 32, 3)
    qkv_mma_kernel<<<qkv_grid, 128, GEMM_SMEM>>>(xh, wh, bq, bk, bv, qscale);

    // V -> transposed fp16
    dim3 tv_grid(NN/64, HH*BB);           // (32, 32)
    transpose_v_kernel<<<tv_grid, 256>>>();

    // Fused attention
    dim3 attn_grid(NN/128, HH, BB);       // (16, 16, 2)
    flash_mma_kernel<<<attn_grid, 128, FLASH_SMEM>>>(mask, ath);

    // Output projection (fp32 out)
    dim3 out_grid(MM/128, ROWS/128);      // (8, 32)
    out_mma_kernel<<<out_grid, 128, GEMM_SMEM>>>(ath, wh + 3*(size_t)MM*MM, bo, out);
}

// round 11
// speedup vs baseline: 7.6287x; 1.0655x over previous
#include <cuda_runtime.h>
#include <cuda_fp16.h>

// Problem constants
#define BB   2
#define NN   2048
#define MM   1024
#define HH   16
#define DKK  64
#define ROWS (BB*NN)   // 4096

// Scratch (allocation-free rule: __device__ globals) — all fp16
__device__ __half g_q [BB*HH*NN*DKK];     // Q, pre-scaled by 0.125*log2(e)
__device__ __half g_k [BB*HH*NN*DKK];
__device__ __half g_v [BB*HH*NN*DKK];
__device__ __half g_vt[BB*HH*DKK*NN];     // V transposed
__device__ __half g_ath[BB*NN*MM];        // attention output (concat layout)
__device__ __half g_xh[ROWS*MM];          // fp16 x
__device__ __half g_wh[4*MM*MM];          // fp16 Wq,Wk,Wv,Wo

// ===========================================================================
// Helpers
// ===========================================================================
__device__ __forceinline__ unsigned smem_u32(const void* p) {
    unsigned a;
    asm("{ .reg .u64 t; cvta.to.shared.u64 t, %1; cvt.u32.u64 %0, t; }"
        : "=r"(a) : "l"(p));
    return a;
}
__device__ __forceinline__ float ex2f(float x) {
    float r;
    asm("ex2.approx.f32 %0, %1;" : "=f"(r) : "f"(x));
    return r;
}
__device__ __forceinline__ unsigned pack_f16(float lo, float hi) {
    unsigned r;
    asm("cvt.rn.f16x2.f32 %0, %1, %2;" : "=r"(r) : "f"(hi), "f"(lo));
    return r;
}
__device__ __forceinline__ void cp16(unsigned dst, const void* src) {
    asm volatile("cp.async.cg.shared.global [%0], [%1], 16;"
                 :: "r"(dst), "l"(src));
}
#define CP_COMMIT() asm volatile("cp.async.commit_group;" ::: "memory")
#define CP_WAIT1()  asm volatile("cp.async.wait_group 1;" ::: "memory")
#define CP_WAIT0()  asm volatile("cp.async.wait_group 0;" ::: "memory")

// ldmatrix: 4 (or 2) 8x8 b16 matrices in one issue.
__device__ __forceinline__ void ldm4(unsigned& r0, unsigned& r1,
                                     unsigned& r2, unsigned& r3, unsigned addr)
{
    asm volatile("ldmatrix.sync.aligned.m8n8.x4.shared.b16 {%0,%1,%2,%3}, [%4];"
                 : "=r"(r0), "=r"(r1), "=r"(r2), "=r"(r3) : "r"(addr));
}
__device__ __forceinline__ void ldm2(unsigned& r0, unsigned& r1, unsigned addr)
{
    asm volatile("ldmatrix.sync.aligned.m8n8.x2.shared.b16 {%0,%1}, [%2];"
                 : "=r"(r0), "=r"(r1) : "r"(addr));
}

// m16n8k16 fp16 MMA, f32 accumulate.
__device__ __forceinline__ void mma16h(float* d, unsigned a0, unsigned a1,
                                       unsigned a2, unsigned a3,
                                       unsigned b0, unsigned b1)
{
    asm("mma.sync.aligned.m16n8k16.row.col.f32.f16.f16.f32 "
        "{%0,%1,%2,%3},{%4,%5,%6,%7},{%8,%9},{%0,%1,%2,%3};"
        : "+f"(d[0]), "+f"(d[1]), "+f"(d[2]), "+f"(d[3])
        : "r"(a0), "r"(a1), "r"(a2), "r"(a3), "r"(b0), "r"(b1));
}

// Lane-constant ldmatrix address offsets (in bytes), stride GSTRH halves.
// A x4: m0 lanes0-7 (rows+0,k+0), m1 lanes8-15 (rows+8,k+0),
//       m2 lanes16-23 (rows+0,k+8), m3 lanes24-31 (rows+8,k+8)
// B x4: m0 (n+0,k+0), m1 (n+0,k+8), m2 (n+8,k+0), m3 (n+8,k+8)
#define GSTRH 72
__device__ __forceinline__ unsigned ldm_aoff(int lane) {
    const int r = (lane & 7) + ((lane >> 3) & 1) * 8;
    const int k = (lane >> 4) * 8;
    return (unsigned)(r * GSTRH + k) * 2u;
}
__device__ __forceinline__ unsigned ldm_boff(int lane) {
    const int r = (lane & 7) + (lane >> 4) * 8;
    const int k = ((lane >> 3) & 1) * 8;
    return (unsigned)(r * GSTRH + k) * 2u;
}
__device__ __forceinline__ unsigned ldm_ooff(int lane) {   // ones rows 64..71, x2
    const int r = 64 + (lane & 7);
    const int k = ((lane >> 3) & 1) * 8;
    return (unsigned)(r * GSTRH + k) * 2u;
}

// ===========================================================================
// Prep: fp32 -> fp16 (rn), elementwise
// ===========================================================================
__global__ __launch_bounds__(256) void cvt_f16_kernel(
    const float* __restrict__ src, __half* __restrict__ dst, int n4)
{
    const int i = blockIdx.x * blockDim.x + threadIdx.x;
    if (i < n4) {
        float4 v = ((const float4*)src)[i];
        uint2 p = { pack_f16(v.x, v.y), pack_f16(v.z, v.w) };
        *(uint2*)(dst + (size_t)i * 4) = p;
    }
}
__global__ __launch_bounds__(256) void cvt_w_kernel(
    const float* __restrict__ W0, const float* __restrict__ W1,
    const float* __restrict__ W2, const float* __restrict__ W3,
    __half* __restrict__ dst)
{
    const int z = blockIdx.y;
    const float* src = (z == 0) ? W0 : (z == 1) ? W1 : (z == 2) ? W2 : W3;
    const int i = blockIdx.x * blockDim.x + threadIdx.x;
    if (i < MM*MM/4) {
        float4 v = ((const float4*)src)[i];
        uint2 p = { pack_f16(v.x, v.y), pack_f16(v.z, v.w) };
        *(uint2*)(dst + (size_t)z * MM * MM + (size_t)i * 4) = p;
    }
}

// ===========================================================================
// Transpose V: g_v [B,H,N,DK] -> g_vt [B,H,DK,N], fp16
// ===========================================================================
__global__ __launch_bounds__(256) void transpose_v_kernel()
{
    __shared__ __half sm[64 * 72];
    const int tid = threadIdx.x;
    const int n0  = blockIdx.x * 64;
    const int bh  = blockIdx.y;

    const __half* Vg = g_v + (size_t)bh * NN * DKK;
    __half* Vt = g_vt + (size_t)bh * DKK * NN;

    #pragma unroll
    for (int u = tid; u < 64 * 32; u += 256) {
        const int r  = u >> 5;
        const int c2 = (u & 31) << 1;
        *(unsigned*)(sm + r * 72 + c2) =
            *(const unsigned*)(Vg + (size_t)(n0 + r) * DKK + c2);
    }
    __syncthreads();

    #pragma unroll
    for (int u = tid; u < 64 * 32; u += 256) {
        const int d = u >> 5;
        const int p = u & 31;
        const unsigned pk = pack_f16(__half2float(sm[(2*p) * 72 + d]),
                                     __half2float(sm[(2*p+1) * 72 + d]));
        *(unsigned*)(Vt + (size_t)d * NN + n0 + 2*p) = pk;
    }
}

// ===========================================================================
// fp16 GEMM body: CTA 128x128, 4 warps, warp tile 64x64, K-chunk 64,
// cp.async double buffer, ldmatrix fragment loads.
// ===========================================================================
#define GBUFH (128*GSTRH)            // 9216 halves per buffer
#define GEMM_SMEM (4*GBUFH*2)        // 73728 bytes

__device__ __forceinline__ void gemm_cp_chunk(
    unsigned sA, unsigned sW,
    const __half* __restrict__ A, const __half* __restrict__ W,
    int tid, int row0, int col0, int chunk)
{
    #pragma unroll
    for (int k = 0; k < 8; k++) {
        const int u = tid + k * 128;
        const int r = u >> 3;
        const int c = u & 7;
        const unsigned soff = (unsigned)(r * GSTRH + c * 8) * 2u;
        cp16(sA + soff, A + (size_t)(row0 + r) * MM + chunk * 64 + c * 8);
        cp16(sW + soff, W + (size_t)(col0 + r) * MM + chunk * 64 + c * 8);
    }
}

template<int HEADED>
__device__ __forceinline__ void gemm_body(
    const __half* __restrict__ A, const __half* __restrict__ W,
    const float* __restrict__ bias, void* __restrict__ Cv, float oscale)
{
    extern __shared__ __half hs[];
    const unsigned sbase = smem_u32(hs);

    const int tid  = threadIdx.x;
    const int w    = tid >> 5;
    const int lane = tid & 31;
    const int g    = lane >> 2;
    const int t    = lane & 3;
    const int row0 = blockIdx.y * 128;
    const int col0 = blockIdx.x * 128;
    const int wm   = (w >> 1) * 64;
    const int wn   = (w & 1) * 64;
    const unsigned aoff = ldm_aoff(lane);
    const unsigned boff = ldm_boff(lane);

    float c[4][8][4] = {};

    gemm_cp_chunk(sbase, sbase + 2*GBUFH*2u, A, W, tid, row0, col0, 0);
    CP_COMMIT();

    for (int i = 0; i < 16; i++) {
        const int cur = i & 1;
        if (i + 1 < 16) {
            const int nxt = (i + 1) & 1;
            gemm_cp_chunk(sbase + nxt*GBUFH*2u, sbase + (2+nxt)*GBUFH*2u,
                          A, W, tid, row0, col0, i + 1);
            CP_COMMIT();
            CP_WAIT1();
        } else {
            CP_WAIT0();
        }
        __syncthreads();

        const unsigned sAb = sbase + (unsigned)cur * GBUFH * 2u;
        const unsigned sWb = sbase + (unsigned)(2 + cur) * GBUFH * 2u;

        #pragma unroll
        for (int ks = 0; ks < 4; ks++) {
            const unsigned kboff = (unsigned)(ks * 16) * 2u;
            unsigned a[4][4];
            #pragma unroll
            for (int mt = 0; mt < 4; mt++)
                ldm4(a[mt][0], a[mt][1], a[mt][2], a[mt][3],
                     sAb + (unsigned)((wm + mt*16) * GSTRH) * 2u + kboff + aoff);
            #pragma unroll
            for (int p = 0; p < 4; p++) {
                unsigned b0, b1, b2, b3;
                ldm4(b0, b1, b2, b3,
                     sWb + (unsigned)((wn + p*16) * GSTRH) * 2u + kboff + boff);
                #pragma unroll
                for (int mt = 0; mt < 4; mt++) {
                    mma16h(c[mt][2*p],   a[mt][0], a[mt][1], a[mt][2], a[mt][3], b0, b1);
                    mma16h(c[mt][2*p+1], a[mt][0], a[mt][1], a[mt][2], a[mt][3], b2, b3);
                }
            }
        }
        __syncthreads();
    }

    // Epilogue
    #pragma unroll
    for (int mt = 0; mt < 4; mt++) {
        const int r0 = row0 + wm + mt * 16 + g;
        const int r1 = r0 + 8;
        #pragma unroll
        for (int nt = 0; nt < 8; nt++) {
            const int col = col0 + wn + nt * 8 + 2 * t;
            const float bx = bias[col], by = bias[col + 1];
            if (HEADED) {
                __half* C = (__half*)Cv;
                const unsigned p0 = pack_f16((c[mt][nt][0] + bx) * oscale,
                                             (c[mt][nt][1] + by) * oscale);
                const unsigned p1 = pack_f16((c[mt][nt][2] + bx) * oscale,
                                             (c[mt][nt][3] + by) * oscale);
                const int h = col >> 6;
                const int d = col & 63;
                const int b0r = r0 >> 11, n0r = r0 & (NN - 1);
                const int b1r = r1 >> 11, n1r = r1 & (NN - 1);
                *(unsigned*)(C + (((size_t)(b0r*HH + h))*NN + n0r)*DKK + d) = p0;
                *(unsigned*)(C + (((size_t)(b1r*HH + h))*NN + n1r)*DKK + d) = p1;
            } else {
                float* C = (float*)Cv;
                float2 v0 = { c[mt][nt][0] + bx, c[mt][nt][1] + by };
                float2 v1 = { c[mt][nt][2] + bx, c[mt][nt][3] + by };
                *(float2*)(C + (size_t)r0 * MM + col) = v0;
                *(float2*)(C + (size_t)r1 * MM + col) = v1;
            }
        }
    }
}

__global__ __launch_bounds__(128, 2) void qkv_mma_kernel(
    const __half* __restrict__ A, const __half* __restrict__ Wt,
    const float* __restrict__ bq, const float* __restrict__ bk,
    const float* __restrict__ bv, float qscale)
{
    const int z = blockIdx.z;
    const __half* W   = Wt + (size_t)z * MM * MM;
    const float* bias = (z == 0) ? bq : (z == 1) ? bk : bv;
    __half*      C    = (z == 0) ? g_q : (z == 1) ? g_k : g_v;
    gemm_body<1>(A, W, bias, C, (z == 0) ? qscale : 1.0f);
}

__global__ __launch_bounds__(128, 2) void out_mma_kernel(
    const __half* __restrict__ A, const __half* __restrict__ W,
    const float* __restrict__ bias, float* __restrict__ C)
{
    gemm_body<0>(A, W, bias, C, 1.0f);
}

// ===========================================================================
// Flash attention, all-fp16 MMA, ldmatrix fragment loads, no online softmax.
// CTA = 128 q-rows, 4 warps. kv tile 64, double-buffered.
// ===========================================================================
#define HQ_OFF  0
#define HK_OFF  9216
#define HKBUF   4608
#define HV_OFF  18432
#define HVBUF   5184
#define FLASH_SMEM (28800 * 2)   // 57600 bytes

__device__ __forceinline__ void flash_cp_q(
    unsigned sQ, const __half* __restrict__ Qg, int tid, int q0)
{
    #pragma unroll
    for (int j = 0; j < 8; j++) {
        const int u = tid + j * 128;
        const int r = u >> 3;
        const int c = u & 7;
        cp16(sQ + (unsigned)(r * GSTRH + c * 8) * 2u,
             Qg + (size_t)(q0 + r) * DKK + c * 8);
    }
}
__device__ __forceinline__ void flash_cp_k(
    unsigned sK, const __half* __restrict__ Kg, int tid, int k0)
{
    #pragma unroll
    for (int j = 0; j < 4; j++) {
        const int u = tid + j * 128;
        const int r = u >> 3;
        const int c = u & 7;
        cp16(sK + (unsigned)(r * GSTRH + c * 8) * 2u,
             Kg + (size_t)(k0 + r) * DKK + c * 8);
    }
}
__device__ __forceinline__ void flash_cp_v(
    unsigned sV, const __half* __restrict__ Vtg, int tid, int k0)
{
    #pragma unroll
    for (int j = 0; j < 4; j++) {
        const int u = tid + j * 128;
        const int d = u >> 3;
        const int c = u & 7;
        cp16(sV + (unsigned)(d * GSTRH + c * 8) * 2u,
             Vtg + (size_t)d * NN + k0 + c * 8);
    }
}

__global__ __launch_bounds__(128, 2) void flash_mma_kernel(
    const float* __restrict__ mask, __half* __restrict__ out)
{
    extern __shared__ __half hs[];
    const unsigned sbase = smem_u32(hs);

    const int tid  = threadIdx.x;
    const int w    = tid >> 5;
    const int lane = tid & 31;
    const int g    = lane >> 2;
    const int t    = lane & 3;
    const int q0   = blockIdx.x * 128;
    const int h    = blockIdx.y;
    const int b    = blockIdx.z;
    const unsigned aoff = ldm_aoff(lane);
    const unsigned boff = ldm_boff(lane);
    const unsigned ooff = ldm_ooff(lane);

    const __half* Qg  = g_q + (((size_t)(b*HH + h)) * NN) * DKK;
    const __half* Kg  = g_k + (((size_t)(b*HH + h)) * NN) * DKK;
    const __half* Vtg = g_vt + (size_t)(b*HH + h) * DKK * NN;
    const float*  Mg  = mask + (size_t)b * NN * NN;

    // V pad rows 64..71 (both buffers): row 64 = 1.0 (ones), rest 0.
    {
        const __half one  = __float2half(1.0f);
        const __half zero = __float2half(0.0f);
        for (int u = tid; u < 8 * GSTRH; u += 128) {
            const int r = 64 + u / GSTRH;
            const int c = u % GSTRH;
            const __half val = (r == 64) ? one : zero;
            hs[HV_OFF + r * GSTRH + c]         = val;
            hs[HV_OFF + HVBUF + r * GSTRH + c] = val;
        }
    }

    flash_cp_q(sbase + HQ_OFF*2u, Qg, tid, q0);
    flash_cp_k(sbase + HK_OFF*2u, Kg, tid, 0);
    flash_cp_v(sbase + HV_OFF*2u, Vtg, tid, 0);
    CP_COMMIT();

    float o[2][8][4] = {};
    float ol[2][4] = {};

    const int qw = q0 + w * 32;

    for (int it = 0; it < 32; it++) {
        const int k0  = it * 64;
        const int cur = it & 1;
        if (it + 1 < 32) {
            const int nxt = (it + 1) & 1;
            flash_cp_k(sbase + (HK_OFF + nxt*HKBUF)*2u, Kg, tid, k0 + 64);
            flash_cp_v(sbase + (HV_OFF + nxt*HVBUF)*2u, Vtg, tid, k0 + 64);
            CP_COMMIT();
            CP_WAIT1();
        } else {
            CP_WAIT0();
        }
        __syncthreads();

        const unsigned sK = sbase + (unsigned)(HK_OFF + cur * HKBUF) * 2u;
        const unsigned sV = sbase + (unsigned)(HV_OFF + cur * HVBUF) * 2u;

        // ---- S~ = Qs * K^T ----
        float s[2][8][4] = {};
        #pragma unroll
        for (int ks = 0; ks < 4; ks++) {
            const unsigned kboff = (unsigned)(ks * 16) * 2u;
            unsigned aq[2][4];
            #pragma unroll
            for (int mt = 0; mt < 2; mt++)
                ldm4(aq[mt][0], aq[mt][1], aq[mt][2], aq[mt][3],
                     sbase + (unsigned)((HQ_OFF + (w*32 + mt*16) * GSTRH)) * 2u
                           + kboff + aoff);
            #pragma unroll
            for (int p = 0; p < 4; p++) {
                unsigned b0, b1, b2, b3;
                ldm4(b0, b1, b2, b3,
                     sK + (unsigned)(p * 16 * GSTRH) * 2u + kboff + boff);
                mma16h(s[0][2*p],   aq[0][0], aq[0][1], aq[0][2], aq[0][3], b0, b1);
                mma16h(s[0][2*p+1], aq[0][0], aq[0][1], aq[0][2], aq[0][3], b2, b3);
                mma16h(s[1][2*p],   aq[1][0], aq[1][1], aq[1][2], aq[1][3], b0, b1);
                mma16h(s[1][2*p+1], aq[1][0], aq[1][1], aq[1][2], aq[1][3], b2, b3);
            }
        }

        // ---- p = exp2(s~ * mask) ----
        #pragma unroll
        for (int mt = 0; mt < 2; mt++) {
            const float* Mr0 = Mg + (size_t)(qw + mt*16 + g) * NN + k0;
            const float* Mr1 = Mr0 + 8 * NN;
            #pragma unroll
            for (int nt = 0; nt < 8; nt++) {
                float2 ma = *(const float2*)(Mr0 + nt * 8 + 2 * t);
                float2 mb = *(const float2*)(Mr1 + nt * 8 + 2 * t);
                s[mt][nt][0] = ex2f(s[mt][nt][0] * ma.x);
                s[mt][nt][1] = ex2f(s[mt][nt][1] * ma.y);
                s[mt][nt][2] = ex2f(s[mt][nt][2] * mb.x);
                s[mt][nt][3] = ex2f(s[mt][nt][3] * mb.y);
            }
        }

        // ---- O += P * V  (A-frags from S C-frags; ldmatrix B) ----
        #pragma unroll
        for (int kk = 0; kk < 4; kk++) {
            unsigned a[2][4];
            #pragma unroll
            for (int mt = 0; mt < 2; mt++) {
                a[mt][0] = pack_f16(s[mt][2*kk][0],   s[mt][2*kk][1]);
                a[mt][1] = pack_f16(s[mt][2*kk][2],   s[mt][2*kk][3]);
                a[mt][2] = pack_f16(s[mt][2*kk+1][0], s[mt][2*kk+1][1]);
                a[mt][3] = pack_f16(s[mt][2*kk+1][2], s[mt][2*kk+1][3]);
            }
            const unsigned kboff = (unsigned)(kk * 16) * 2u;
            #pragma unroll
            for (int p = 0; p < 4; p++) {
                unsigned b0, b1, b2, b3;
                ldm4(b0, b1, b2, b3,
                     sV + (unsigned)(p * 16 * GSTRH) * 2u + kboff + boff);
                mma16h(o[0][2*p],   a[0][0], a[0][1], a[0][2], a[0][3], b0, b1);
                mma16h(o[0][2*p+1], a[0][0], a[0][1], a[0][2], a[0][3], b2, b3);
                mma16h(o[1][2*p],   a[1][0], a[1][1], a[1][2], a[1][3], b0, b1);
                mma16h(o[1][2*p+1], a[1][0], a[1][1], a[1][2], a[1][3], b2, b3);
            }
            {
                unsigned b0, b1;
                ldm2(b0, b1, sV + kboff + ooff);
                mma16h(ol[0], a[0][0], a[0][1], a[0][2], a[0][3], b0, b1);
                mma16h(ol[1], a[1][0], a[1][1], a[1][2], a[1][3], b0, b1);
            }
        }
        __syncthreads();
    }

    // ---- l broadcast + normalize + write concat [B,N,M] fp16 ----
    #pragma unroll
    for (int mt = 0; mt < 2; mt++) {
        const float l0 = __shfl_sync(0xffffffffu, ol[mt][0], lane & 28);
        const float l1 = __shfl_sync(0xffffffffu, ol[mt][2], lane & 28);
        const float il0 = 1.0f / l0;
        const float il1 = 1.0f / l1;
        __half* Or0 = out + ((size_t)b * NN + qw + mt*16 + g) * MM + h * DKK;
        __half* Or1 = Or0 + 8 * MM;
        #pragma unroll
        for (int nt = 0; nt < 8; nt++) {
            const unsigned p0 = pack_f16(o[mt][nt][0] * il0, o[mt][nt][1] * il0);
            const unsigned p1 = pack_f16(o[mt][nt][2] * il1, o[mt][nt][3] * il1);
            *(unsigned*)(Or0 + nt * 8 + 2 * t) = p0;
            *(unsigned*)(Or1 + nt * 8 + 2 * t) = p1;
        }
    }
}

// ===========================================================================
extern "C" void kernel_launch(void* const* d_in, const int* in_sizes, int n_in,
                              void* d_out, int out_size)
{
    const float* x    = (const float*)d_in[0];
    const float* mask = (const float*)d_in[1];
    const float* Wq   = (const float*)d_in[2];
    const float* bq   = (const float*)d_in[3];
    const float* Wk   = (const float*)d_in[4];
    const float* bk   = (const float*)d_in[5];
    const float* Wv   = (const float*)d_in[6];
    const float* bv   = (const float*)d_in[7];
    const float* Wo   = (const float*)d_in[8];
    const float* bo   = (const float*)d_in[9];
    float* out = (float*)d_out;

    void *pxh, *pwh, *path;
    cudaGetSymbolAddress(&pxh,  g_xh);
    cudaGetSymbolAddress(&pwh,  g_wh);
    cudaGetSymbolAddress(&path, g_ath);
    __half* xh  = (__half*)pxh;
    __half* wh  = (__half*)pwh;
    __half* ath = (__half*)path;

    cudaFuncSetAttribute(qkv_mma_kernel,
                         cudaFuncAttributeMaxDynamicSharedMemorySize, GEMM_SMEM);
    cudaFuncSetAttribute(out_mma_kernel,
                         cudaFuncAttributeMaxDynamicSharedMemorySize, GEMM_SMEM);
    cudaFuncSetAttribute(flash_mma_kernel,
                         cudaFuncAttributeMaxDynamicSharedMemorySize, FLASH_SMEM);

    // Convert inputs to fp16 once.
    cvt_f16_kernel<<<(ROWS*MM/4 + 255)/256, 256>>>(x, xh, ROWS*MM/4);
    dim3 w_grid((MM*MM/4 + 255)/256, 4);
    cvt_w_kernel<<<w_grid, 256>>>(Wq, Wk, Wv, Wo, wh);

    // Fused Q/K/V projections (Q pre-scaled by 0.125*log2(e))
    const float qscale = 0.125f * 1.4426950408889634f;
    dim3 qkv_grid(MM/128, ROWS/128, 3);   // (8, 32, 3)
    qkv_mma_kernel<<<qkv_grid, 128, GEMM_SMEM>>>(xh, wh, bq, bk, bv, qscale);

    // V -> transposed fp16
    dim3 tv_grid(NN/64, HH*BB);           // (32, 32)
    transpose_v_kernel<<<tv_grid, 256>>>();

    // Fused attention
    dim3 attn_grid(NN/128, HH, BB);       // (16, 16, 2)
    flash_mma_kernel<<<attn_grid, 128, FLASH_SMEM>>>(mask, ath);

    // Output projection (fp32 out)
    dim3 out_grid(MM/128, ROWS/128);      // (8, 32)
    out_mma_kernel<<<out_grid, 128, GEMM_SMEM>>>(ath, wh + 3*(size_t)MM*MM, bo, out);
}